// round 1
// baseline (speedup 1.0000x reference)
#include <cuda_runtime.h>

#define B_   2
#define LSEQ 768
#define SIN  1280
#define SOUT 32
#define ZF   32
#define DI   64
#define DS   16
#define NCH  24     // chunks along L
#define CT   32     // chunk length (NCH*CT = LSEQ)
#define NROWS (B_*LSEQ)          // 1536
#define CHAINS (B_*DI*DS)        // 2048

// ---------------- scratch (device globals; no allocation allowed) ----------
__device__ float g_WcT[SIN*128];        // combined in_proj∘s_proj, transposed [i][j]
__device__ float g_bc[128];             // combined bias
__device__ float g_xpre[NROWS*DI];      // x before conv
__device__ float g_gate[NROWS*DI];      // gate (raw)
__device__ float g_x[NROWS*DI];         // x after conv+silu
__device__ float g_dt[NROWS*DI];        // softplus(dt)
__device__ float g_Bm[NROWS*DS];
__device__ float g_Cm[NROWS*DS];
__device__ float g_ca[CHAINS*NCH];      // chunk transfer a = prod dA
__device__ float g_cb[CHAINS*NCH];      // chunk offset  b
__device__ float g_hi[CHAINS*NCH];      // h at chunk entry

// ---------------- K0: combined weights Wc = in_proj @ s_proj ---------------
__global__ void k0_weights(const float* __restrict__ sw, const float* __restrict__ sb,
                           const float* __restrict__ inw) {
    int idx = blockIdx.x * 256 + threadIdx.x;
    if (idx < SIN * 128) {
        int i = idx >> 7, j = idx & 127;
        float acc = 0.f;
        #pragma unroll
        for (int k = 0; k < SOUT; k++) acc += inw[j*SOUT + k] * sw[k*SIN + i];
        g_WcT[i*128 + j] = acc;
    }
    if (idx < 128) {
        float acc = 0.f;
        #pragma unroll
        for (int k = 0; k < SOUT; k++) acc += inw[idx*SOUT + k] * sb[k];
        g_bc[idx] = acc;
    }
}

// ---------------- K1: xz = s @ WcT + bc  (the big GEMM) --------------------
// block: 128 threads = 8 rows (ty) x 16 j-groups (tx, 8 j each). grid: 192.
__global__ void __launch_bounds__(128) k1_inproj(const float* __restrict__ s) {
    __shared__ float ss[8][SIN];
    int tid = threadIdx.x;
    int r0 = blockIdx.x * 8;
    for (int idx = tid; idx < 8 * SIN; idx += 128) {
        int r = idx / SIN, i = idx % SIN;
        ss[r][i] = s[(size_t)(r0 + r) * SIN + i];
    }
    __syncthreads();
    int ty = tid >> 4, tx = tid & 15;
    int j0 = tx * 8;
    unsigned long long acc0 = 0, acc1 = 0, acc2 = 0, acc3 = 0; // = (0.f,0.f) packed
    const float* wp = g_WcT + j0;
    #pragma unroll 4
    for (int i = 0; i < SIN; i++) {
        float sv = ss[ty][i];
        unsigned int sbits = __float_as_uint(sv);
        unsigned long long a;
        asm("mov.b64 %0, {%1,%1};" : "=l"(a) : "r"(sbits));
        ulonglong2 wa = *(const ulonglong2*)(wp + i * 128);      // j0..j0+3
        ulonglong2 wb = *(const ulonglong2*)(wp + i * 128 + 4);  // j0+4..j0+7
        asm("fma.rn.f32x2 %0, %1, %2, %0;" : "+l"(acc0) : "l"(a), "l"(wa.x));
        asm("fma.rn.f32x2 %0, %1, %2, %0;" : "+l"(acc1) : "l"(a), "l"(wa.y));
        asm("fma.rn.f32x2 %0, %1, %2, %0;" : "+l"(acc2) : "l"(a), "l"(wb.x));
        asm("fma.rn.f32x2 %0, %1, %2, %0;" : "+l"(acc3) : "l"(a), "l"(wb.y));
    }
    float2 q0 = *(float2*)&acc0, q1 = *(float2*)&acc1;
    float2 q2 = *(float2*)&acc2, q3 = *(float2*)&acc3;
    float4 b0 = *(const float4*)(g_bc + j0);
    float4 b1 = *(const float4*)(g_bc + j0 + 4);
    float4 o0 = make_float4(q0.x + b0.x, q0.y + b0.y, q1.x + b0.z, q1.y + b0.w);
    float4 o1 = make_float4(q2.x + b1.x, q2.y + b1.y, q3.x + b1.z, q3.y + b1.w);
    int row = r0 + ty;
    if (j0 < DI) {
        *(float4*)(g_xpre + row * DI + j0)     = o0;
        *(float4*)(g_xpre + row * DI + j0 + 4) = o1;
    } else {
        *(float4*)(g_gate + row * DI + (j0 - DI))     = o0;
        *(float4*)(g_gate + row * DI + (j0 - DI) + 4) = o1;
    }
}

// ---------------- K2: conv1d + silu + x_proj + dt ---------------------------
__global__ void __launch_bounds__(64) k2_conv(const float* __restrict__ convw,
                                              const float* __restrict__ convb,
                                              const float* __restrict__ xpw,
                                              const float* __restrict__ dtw,
                                              const float* __restrict__ dtb) {
    int row = blockIdx.x;
    int l = row % LSEQ;
    int d = threadIdx.x;
    __shared__ float xs[DI];
    __shared__ float xd[34];
    float acc = convb[d];
    #pragma unroll
    for (int k = 0; k < 4; k++) {
        int ls = l + k - 3;
        if (ls >= 0) acc += g_xpre[(row + k - 3) * DI + d] * convw[d * 4 + k];
    }
    float xv = acc / (1.f + __expf(-acc));   // silu
    xs[d] = xv;
    __syncthreads();
    if (d < 34) {
        float a = 0.f;
        #pragma unroll
        for (int j = 0; j < DI; j++) a += xs[j] * xpw[d * DI + j];
        xd[d] = a;
    }
    __syncthreads();
    float dtraw = xd[0] * dtw[d * 2] + xd[1] * dtw[d * 2 + 1] + dtb[d];
    float dtv = fmaxf(dtraw, 0.f) + log1pf(__expf(-fabsf(dtraw))); // softplus, stable
    g_x[row * DI + d]  = xv;
    g_dt[row * DI + d] = dtv;
    if (d < DS)            g_Bm[row * DS + d]        = xd[2 + d];
    else if (d < 2 * DS)   g_Cm[row * DS + (d - DS)] = xd[18 + (d - DS)];
}

// ---------------- K4: per-chunk scan summaries (a = prod dA, b = local h) --
__global__ void __launch_bounds__(1024) k4_chunk(const float* __restrict__ A_log) {
    int b = blockIdx.x / NCH, c = blockIdx.x % NCH;
    int tid = threadIdx.x;
    int d = tid >> 4, n = tid & 15;
    __shared__ float sdt[CT][DI], sx[CT][DI], sB[CT][DS];
    int base = b * LSEQ + c * CT;
    for (int idx = tid; idx < CT * DI; idx += 1024) {
        int t = idx / DI, dd = idx % DI;
        sdt[t][dd] = g_dt[(base + t) * DI + dd];
        sx[t][dd]  = g_x[(base + t) * DI + dd];
    }
    for (int idx = tid; idx < CT * DS; idx += 1024) {
        int t = idx / DS, nn = idx % DS;
        sB[t][nn] = g_Bm[(base + t) * DS + nn];
    }
    __syncthreads();
    float a = -__expf(A_log[d * DS + n]);
    float ra = 1.f, rb = 0.f;
    #pragma unroll 8
    for (int t = 0; t < CT; t++) {
        float dtv = sdt[t][d];
        float dA  = __expf(dtv * a);
        float dbu = dtv * sB[t][n] * sx[t][d];
        ra *= dA;
        rb = dA * rb + dbu;
    }
    int chain = (b * DI + d) * DS + n;
    g_ca[chain * NCH + c] = ra;
    g_cb[chain * NCH + c] = rb;
}

// ---------------- K5: combine chunk summaries -> entry states --------------
__global__ void __launch_bounds__(1024) k5_combine() {
    int chain = blockIdx.x * 1024 + threadIdx.x;
    float h = 0.f;
    #pragma unroll
    for (int c = 0; c < NCH; c++) {
        g_hi[chain * NCH + c] = h;
        h = g_ca[chain * NCH + c] * h + g_cb[chain * NCH + c];
    }
}

// ---------------- K6: scan pass 2 + D-skip + gate + out_proj ---------------
__global__ void __launch_bounds__(1024) k6_scan(const float* __restrict__ A_log,
                                                const float* __restrict__ Dp,
                                                const float* __restrict__ opw,
                                                float* __restrict__ out) {
    int b = blockIdx.x / NCH, c = blockIdx.x % NCH;
    int tid = threadIdx.x;
    int d = tid >> 4, n = tid & 15;
    __shared__ float sdt[CT][DI], sx[CT][DI], sg[CT][DI];
    __shared__ float sB[CT][DS], sC[CT][DS];
    __shared__ float ysm[CT][DI];
    __shared__ float sop[SOUT][DI + 1];   // padded: conflict-free column reads
    int base = b * LSEQ + c * CT;
    for (int idx = tid; idx < CT * DI; idx += 1024) {
        int t = idx / DI, dd = idx % DI;
        sdt[t][dd] = g_dt[(base + t) * DI + dd];
        sx[t][dd]  = g_x[(base + t) * DI + dd];
        sg[t][dd]  = g_gate[(base + t) * DI + dd];
    }
    for (int idx = tid; idx < CT * DS; idx += 1024) {
        int t = idx / DS, nn = idx % DS;
        sB[t][nn] = g_Bm[(base + t) * DS + nn];
        sC[t][nn] = g_Cm[(base + t) * DS + nn];
    }
    for (int idx = tid; idx < SOUT * DI; idx += 1024)
        sop[idx / DI][idx % DI] = opw[idx];
    __syncthreads();

    float a = -__expf(A_log[d * DS + n]);
    int chain = (b * DI + d) * DS + n;
    float h  = g_hi[chain * NCH + c];
    float Dv = Dp[d];
    for (int t = 0; t < CT; t++) {
        float dtv = sdt[t][d];
        float dA  = __expf(dtv * a);
        float dbu = dtv * sB[t][n] * sx[t][d];
        h = dA * h + dbu;
        float cb_ = h * sC[t][n];
        cb_ += __shfl_xor_sync(0xffffffffu, cb_, 8);
        cb_ += __shfl_xor_sync(0xffffffffu, cb_, 4);
        cb_ += __shfl_xor_sync(0xffffffffu, cb_, 2);
        cb_ += __shfl_xor_sync(0xffffffffu, cb_, 1);
        if (n == 0) {
            float y = cb_ + sx[t][d] * Dv;
            float g = sg[t][d];
            y *= g / (1.f + __expf(-g));
            ysm[t][d] = y;
        }
    }
    __syncthreads();
    // out_proj: 1024 threads = 32 t x 32 f
    int t = tid >> 5, f = tid & 31;
    float acc = 0.f;
    #pragma unroll
    for (int dd = 0; dd < DI; dd++) acc += ysm[t][dd] * sop[f][dd];
    out[(size_t)(base + t) * SOUT + f] = acc;
}

// ---------------- K7: z_prime = z*zw + zb + outer(sp, sp) ------------------
// grid: B_*(LSEQ/8) blocks; block (8,32). Each block: 8 s-rows x all t.
__global__ void __launch_bounds__(256) k7_z(const float* __restrict__ z,
                                            const float* __restrict__ zw,
                                            const float* __restrict__ zbv,
                                            const float* __restrict__ sp,
                                            float* __restrict__ outz) {
    int blk = blockIdx.x;
    int b = blk / (LSEQ / 8);
    int s0 = (blk % (LSEQ / 8)) * 8;
    int tx = threadIdx.x;   // 0..7  (f/4)
    int ty = threadIdx.y;   // 0..31 (t lane)
    float4 zw4 = ((const float4*)zw)[tx];
    float4 zb4 = ((const float4*)zbv)[tx];
    float4 sps[8];
    #pragma unroll
    for (int si = 0; si < 8; si++)
        sps[si] = ((const float4*)(sp + (size_t)(b * LSEQ + s0 + si) * SOUT))[tx];
    const float* zrow = z + (size_t)(b * LSEQ) * LSEQ;
    float* orow = outz + (size_t)(b * LSEQ) * LSEQ * ZF;
    for (int t0 = 0; t0 < LSEQ; t0 += 32) {
        int t = t0 + ty;
        float4 spt = ((const float4*)(sp + (size_t)(b * LSEQ + t) * SOUT))[tx];
        #pragma unroll
        for (int si = 0; si < 8; si++) {
            float zv = zrow[(size_t)(s0 + si) * LSEQ + t];
            float4 o;
            o.x = fmaf(zv, zw4.x, zb4.x) + sps[si].x * spt.x;
            o.y = fmaf(zv, zw4.y, zb4.y) + sps[si].y * spt.y;
            o.z = fmaf(zv, zw4.z, zb4.z) + sps[si].z * spt.z;
            o.w = fmaf(zv, zw4.w, zb4.w) + sps[si].w * spt.w;
            ((float4*)(orow + ((size_t)(s0 + si) * LSEQ + t) * ZF))[tx] = o;
        }
    }
}

// ---------------- launch ----------------------------------------------------
extern "C" void kernel_launch(void* const* d_in, const int* in_sizes, int n_in,
                              void* d_out, int out_size) {
    const float* s        = (const float*)d_in[0];
    const float* z        = (const float*)d_in[1];
    const float* s_proj_w = (const float*)d_in[2];
    const float* s_proj_b = (const float*)d_in[3];
    const float* z_proj_w = (const float*)d_in[4];
    const float* z_proj_b = (const float*)d_in[5];
    const float* in_proj_w= (const float*)d_in[6];
    const float* conv_w   = (const float*)d_in[7];
    const float* conv_b   = (const float*)d_in[8];
    const float* x_proj_w = (const float*)d_in[9];
    const float* dt_proj_w= (const float*)d_in[10];
    const float* dt_proj_b= (const float*)d_in[11];
    const float* A_log    = (const float*)d_in[12];
    const float* Dp       = (const float*)d_in[13];
    const float* out_proj_w = (const float*)d_in[14];

    float* out    = (float*)d_out;
    float* sp_out = out;                       // [2,768,32]
    float* z_out  = out + (size_t)B_ * LSEQ * SOUT;

    k0_weights<<<(SIN * 128 + 255) / 256, 256>>>(s_proj_w, s_proj_b, in_proj_w);
    k1_inproj<<<NROWS / 8, 128>>>(s);
    k2_conv<<<NROWS, 64>>>(conv_w, conv_b, x_proj_w, dt_proj_w, dt_proj_b);
    k4_chunk<<<B_ * NCH, 1024>>>(A_log);
    k5_combine<<<CHAINS / 1024, 1024>>>();
    k6_scan<<<B_ * NCH, 1024>>>(A_log, Dp, out_proj_w, sp_out);
    k7_z<<<B_ * (LSEQ / 8), dim3(8, 32)>>>(z, z_proj_w, z_proj_b, sp_out, z_out);
}

// round 2
// speedup vs baseline: 1.2581x; 1.2581x over previous
#include <cuda_runtime.h>

#define B_   2
#define LSEQ 768
#define SIN  1280
#define SOUT 32
#define ZF   32
#define DI   64
#define DS   16
#define NCH  48     // chunks along L
#define CT   16     // chunk length (NCH*CT = LSEQ)
#define NROWS (B_*LSEQ)          // 1536
#define CHAINS (B_*DI*DS)        // 2048
#define KS   16     // split-K factor for K1
#define KC   (SIN/KS)            // 80
#define KT   16     // k sub-tile staged in smem

// ---------------- scratch (device globals; no allocation allowed) ----------
__device__ float g_WcT[SIN*128];        // combined in_proj . s_proj, [i][j]
__device__ float g_bc[128];             // combined bias
__device__ float g_part[KS*NROWS*128];  // split-K partials (12.6 MB)
__device__ float g_xpre[NROWS*DI];      // x before conv
__device__ float g_gate[NROWS*DI];      // gate (raw)
__device__ float g_x[NROWS*DI];         // x after conv+silu
__device__ float g_dt[NROWS*DI];        // softplus(dt)
__device__ float g_Bm[NROWS*DS];
__device__ float g_Cm[NROWS*DS];
__device__ float g_dA[NROWS*1024];      // exp(dt*A)   [t][chain-within-batch]
__device__ float g_dbu[NROWS*1024];     // dt*B*x
__device__ float g_ca[NCH*CHAINS];      // chunk transfer a  ([c][chain], coalesced)
__device__ float g_cb[NCH*CHAINS];      // chunk offset  b
__device__ float g_hi[NCH*CHAINS];      // h at chunk entry

// ---------------- K0: combined weights Wc = in_proj @ s_proj ---------------
__global__ void k0_weights(const float* __restrict__ sw, const float* __restrict__ sb,
                           const float* __restrict__ inw) {
    int idx = blockIdx.x * 256 + threadIdx.x;
    if (idx < SIN * 128) {
        int i = idx >> 7, j = idx & 127;
        float acc = 0.f;
        #pragma unroll
        for (int k = 0; k < SOUT; k++) acc += inw[j*SOUT + k] * sw[k*SIN + i];
        g_WcT[i*128 + j] = acc;
    }
    if (idx < 128) {
        float acc = 0.f;
        #pragma unroll
        for (int k = 0; k < SOUT; k++) acc += inw[idx*SOUT + k] * sb[k];
        g_bc[idx] = acc;
    }
}

// ---------------- K1a: split-K register-tiled GEMM -------------------------
// grid = 12 row-tiles x KS ksplits = 192 blocks, 256 threads.
// Tile: 128 rows x 128 cols, 8x8 per thread, packed f32x2 FMAs.
// Weights stored DUPLICATED in smem so {w,w} pairs load directly (no movs).
__global__ void __launch_bounds__(256) k1a_gemm(const float* __restrict__ s) {
    __shared__ float ss[KT][132];     // [kk][row], padded
    __shared__ float ws2[KT][256];    // [kk][2*j] duplicated weights
    int tid = threadIdx.x;
    int rt = blockIdx.x >> 4;
    int ks = blockIdx.x & 15;
    int r0 = rt * 128;
    int kb = ks * KC;
    int tx = tid & 15, ty = tid >> 4;
    int j0 = tx * 8;       // 8 cols per thread
    int row0 = ty * 8;     // 8 rows per thread

    // item decomposition (2 items per thread per array, 512 each)
    int it0 = tid, it1 = tid + 256;
    int sr0 = it0 >> 2, skg0 = it0 & 3;
    int sr1 = it1 >> 2, skg1 = it1 & 3;
    int wkk0 = it0 >> 5, wjg0 = it0 & 31;
    int wkk1 = it1 >> 5, wjg1 = it1 & 31;

    float4 sv0, sv1, wv0, wv1;
    sv0 = *(const float4*)(s + (size_t)(r0 + sr0)*SIN + kb + skg0*4);
    sv1 = *(const float4*)(s + (size_t)(r0 + sr1)*SIN + kb + skg1*4);
    wv0 = *(const float4*)(g_WcT + (size_t)(kb + wkk0)*128 + wjg0*4);
    wv1 = *(const float4*)(g_WcT + (size_t)(kb + wkk1)*128 + wjg1*4);

    unsigned long long acc[4][8];
    #pragma unroll
    for (int r = 0; r < 4; r++)
        #pragma unroll
        for (int j = 0; j < 8; j++) acc[r][j] = 0ull;

    #pragma unroll 1
    for (int tile = 0; tile < KC/KT; tile++) {
        // commit staged regs to smem
        ss[skg0*4+0][sr0] = sv0.x; ss[skg0*4+1][sr0] = sv0.y;
        ss[skg0*4+2][sr0] = sv0.z; ss[skg0*4+3][sr0] = sv0.w;
        ss[skg1*4+0][sr1] = sv1.x; ss[skg1*4+1][sr1] = sv1.y;
        ss[skg1*4+2][sr1] = sv1.z; ss[skg1*4+3][sr1] = sv1.w;
        *(float4*)&ws2[wkk0][wjg0*8]   = make_float4(wv0.x, wv0.x, wv0.y, wv0.y);
        *(float4*)&ws2[wkk0][wjg0*8+4] = make_float4(wv0.z, wv0.z, wv0.w, wv0.w);
        *(float4*)&ws2[wkk1][wjg1*8]   = make_float4(wv1.x, wv1.x, wv1.y, wv1.y);
        *(float4*)&ws2[wkk1][wjg1*8+4] = make_float4(wv1.z, wv1.z, wv1.w, wv1.w);
        __syncthreads();
        if (tile < KC/KT - 1) {
            int kb2 = kb + (tile+1)*KT;
            sv0 = *(const float4*)(s + (size_t)(r0 + sr0)*SIN + kb2 + skg0*4);
            sv1 = *(const float4*)(s + (size_t)(r0 + sr1)*SIN + kb2 + skg1*4);
            wv0 = *(const float4*)(g_WcT + (size_t)(kb2 + wkk0)*128 + wjg0*4);
            wv1 = *(const float4*)(g_WcT + (size_t)(kb2 + wkk1)*128 + wjg1*4);
        }
        #pragma unroll
        for (int kk = 0; kk < KT; kk++) {
            ulonglong2 sA = *(const ulonglong2*)&ss[kk][row0];     // rows 0-3 as 2 pairs
            ulonglong2 sB_ = *(const ulonglong2*)&ss[kk][row0+4];  // rows 4-7
            ulonglong2 w01 = *(const ulonglong2*)&ws2[kk][j0*2];
            ulonglong2 w23 = *(const ulonglong2*)&ws2[kk][j0*2+4];
            ulonglong2 w45 = *(const ulonglong2*)&ws2[kk][j0*2+8];
            ulonglong2 w67 = *(const ulonglong2*)&ws2[kk][j0*2+12];
            unsigned long long sp[4] = {sA.x, sA.y, sB_.x, sB_.y};
            unsigned long long wd[8] = {w01.x, w01.y, w23.x, w23.y,
                                        w45.x, w45.y, w67.x, w67.y};
            #pragma unroll
            for (int r = 0; r < 4; r++)
                #pragma unroll
                for (int j = 0; j < 8; j++)
                    asm("fma.rn.f32x2 %0, %1, %2, %0;"
                        : "+l"(acc[r][j]) : "l"(sp[r]), "l"(wd[j]));
        }
        __syncthreads();
    }
    // epilogue: write partials
    #pragma unroll
    for (int rr = 0; rr < 8; rr++) {
        float f[8];
        #pragma unroll
        for (int j = 0; j < 8; j++) {
            float2 q = *(float2*)&acc[rr>>1][j];
            f[j] = (rr & 1) ? q.y : q.x;
        }
        size_t o = ((size_t)ks*NROWS + r0 + row0 + rr)*128 + j0;
        *(float4*)(g_part + o)     = make_float4(f[0], f[1], f[2], f[3]);
        *(float4*)(g_part + o + 4) = make_float4(f[4], f[5], f[6], f[7]);
    }
}

// ---------------- K1b: reduce split-K partials + bias ----------------------
__global__ void __launch_bounds__(256) k1b_reduce() {
    int idx = blockIdx.x * 256 + threadIdx.x;   // < 196608
    float acc = g_bc[idx & 127];
    #pragma unroll
    for (int k = 0; k < KS; k++) acc += g_part[(size_t)k*NROWS*128 + idx];
    int j = idx & 127, row = idx >> 7;
    if (j < DI) g_xpre[row*DI + j] = acc;
    else        g_gate[row*DI + (j - DI)] = acc;
}

// ---------------- K2: conv1d + silu + x_proj + dt ---------------------------
__global__ void __launch_bounds__(64) k2_conv(const float* __restrict__ convw,
                                              const float* __restrict__ convb,
                                              const float* __restrict__ xpw,
                                              const float* __restrict__ dtw,
                                              const float* __restrict__ dtb) {
    int row = blockIdx.x;
    int l = row % LSEQ;
    int d = threadIdx.x;
    __shared__ float xs[DI];
    __shared__ float xd[34];
    float acc = convb[d];
    #pragma unroll
    for (int k = 0; k < 4; k++) {
        int ls = l + k - 3;
        if (ls >= 0) acc += g_xpre[(row + k - 3) * DI + d] * convw[d * 4 + k];
    }
    float xv = acc / (1.f + __expf(-acc));   // silu
    xs[d] = xv;
    __syncthreads();
    if (d < 34) {
        float a = 0.f;
        #pragma unroll
        for (int j = 0; j < DI; j++) a += xs[j] * xpw[d * DI + j];
        xd[d] = a;
    }
    __syncthreads();
    float dtraw = xd[0] * dtw[d * 2] + xd[1] * dtw[d * 2 + 1] + dtb[d];
    float dtv = fmaxf(dtraw, 0.f) + log1pf(__expf(-fabsf(dtraw))); // softplus
    g_x[row * DI + d]  = xv;
    g_dt[row * DI + d] = dtv;
    if (d < DS)            g_Bm[row * DS + d]        = xd[2 + d];
    else if (d < 2 * DS)   g_Cm[row * DS + (d - DS)] = xd[18 + (d - DS)];
}

// ---------------- K4: per-chunk scan summaries + materialize dA/dbu --------
__global__ void __launch_bounds__(1024) k4_chunk(const float* __restrict__ A_log) {
    int b = blockIdx.x / NCH, c = blockIdx.x % NCH;
    int tid = threadIdx.x;
    int d = tid >> 4, n = tid & 15;
    __shared__ float sdt[CT][DI], sx[CT][DI], sB[CT][DS];
    int base = b * LSEQ + c * CT;
    { int t = tid >> 6, dd = tid & 63;              // CT*DI == 1024
      sdt[t][dd] = g_dt[(base + t) * DI + dd];
      sx[t][dd]  = g_x[(base + t) * DI + dd]; }
    if (tid < CT * DS) { int t = tid >> 4, nn = tid & 15;
      sB[t][nn] = g_Bm[(base + t) * DS + nn]; }
    __syncthreads();
    float a = -__expf(A_log[d * DS + n]);
    float ra = 1.f, rb = 0.f;
    int chain = b * 1024 + tid;
    #pragma unroll
    for (int t = 0; t < CT; t++) {
        float dtv = sdt[t][d];
        float dA  = __expf(dtv * a);
        float dbu = dtv * sB[t][n] * sx[t][d];
        g_dA [(size_t)(base + t) * 1024 + tid] = dA;
        g_dbu[(size_t)(base + t) * 1024 + tid] = dbu;
        ra *= dA;
        rb = fmaf(dA, rb, dbu);
    }
    g_ca[c * CHAINS + chain] = ra;
    g_cb[c * CHAINS + chain] = rb;
}

// ---------------- K5: combine chunk summaries -> entry states --------------
__global__ void __launch_bounds__(1024) k5_combine() {
    int chain = blockIdx.x * 1024 + threadIdx.x;
    float h = 0.f;
    #pragma unroll 8
    for (int c = 0; c < NCH; c++) {
        g_hi[c * CHAINS + chain] = h;
        h = fmaf(g_ca[c * CHAINS + chain], h, g_cb[c * CHAINS + chain]);
    }
}

// ---------------- K6: scan pass 2 + D-skip + gate + out_proj ---------------
__global__ void __launch_bounds__(1024) k6_scan(const float* __restrict__ Dp,
                                                const float* __restrict__ opw,
                                                float* __restrict__ out) {
    int b = blockIdx.x / NCH, c = blockIdx.x % NCH;
    int tid = threadIdx.x;
    int d = tid >> 4, n = tid & 15;
    __shared__ float sx[CT][DI], sg[CT][DI], sC[CT][DS];
    __shared__ float ysm[CT][DI];
    __shared__ float sop[SOUT][DI + 1];
    int base = b * LSEQ + c * CT;
    { int t = tid >> 6, dd = tid & 63;
      sx[t][dd] = g_x[(base + t) * DI + dd];
      sg[t][dd] = g_gate[(base + t) * DI + dd]; }
    if (tid < CT * DS) { int t = tid >> 4, nn = tid & 15;
      sC[t][nn] = g_Cm[(base + t) * DS + nn]; }
    for (int idx = tid; idx < SOUT * DI; idx += 1024)
        sop[idx >> 6][idx & 63] = opw[idx];
    float rdA[CT], rdbu[CT];
    #pragma unroll
    for (int t = 0; t < CT; t++) {
        rdA [t] = g_dA [(size_t)(base + t) * 1024 + tid];
        rdbu[t] = g_dbu[(size_t)(base + t) * 1024 + tid];
    }
    int chain = b * 1024 + tid;
    float h  = g_hi[c * CHAINS + chain];
    float Dv = Dp[d];
    __syncthreads();
    #pragma unroll
    for (int t = 0; t < CT; t++) {
        h = fmaf(rdA[t], h, rdbu[t]);
        float cb_ = h * sC[t][n];
        cb_ += __shfl_xor_sync(0xffffffffu, cb_, 8);
        cb_ += __shfl_xor_sync(0xffffffffu, cb_, 4);
        cb_ += __shfl_xor_sync(0xffffffffu, cb_, 2);
        cb_ += __shfl_xor_sync(0xffffffffu, cb_, 1);
        if (n == 0) {
            float y = cb_ + sx[t][d] * Dv;
            float g = sg[t][d];
            y *= g / (1.f + __expf(-g));
            ysm[t][d] = y;
        }
    }
    __syncthreads();
    if (tid < CT * SOUT) {      // 512 threads: 16 t x 32 f
        int t = tid >> 5, f = tid & 31;
        float acc = 0.f;
        #pragma unroll
        for (int dd = 0; dd < DI; dd++) acc = fmaf(ysm[t][dd], sop[f][dd], acc);
        out[(size_t)(base + t) * SOUT + f] = acc;
    }
}

// ---------------- K7: z_prime = z*zw + zb + outer(sp, sp) ------------------
// 768 blocks: b x 96 s-groups x 4 t-quarters. block (8,32).
__global__ void __launch_bounds__(256) k7_z(const float* __restrict__ z,
                                            const float* __restrict__ zw,
                                            const float* __restrict__ zbv,
                                            const float* __restrict__ sp,
                                            float* __restrict__ outz) {
    int blk = blockIdx.x;
    int b = blk / 384;
    int rem = blk % 384;
    int s0 = (rem >> 2) * 8;
    int tq = rem & 3;
    int tx = threadIdx.x;   // 0..7  (f/4)
    int ty = threadIdx.y;   // 0..31 (t lane)
    float4 zw4 = ((const float4*)zw)[tx];
    float4 zb4 = ((const float4*)zbv)[tx];
    float4 sps[8];
    #pragma unroll
    for (int si = 0; si < 8; si++)
        sps[si] = ((const float4*)(sp + (size_t)(b * LSEQ + s0 + si) * SOUT))[tx];
    const float* zrow = z + (size_t)(b * LSEQ) * LSEQ;
    float* orow = outz + (size_t)(b * LSEQ) * LSEQ * ZF;
    for (int t0 = tq * 192; t0 < (tq + 1) * 192; t0 += 32) {
        int t = t0 + ty;
        float4 spt = ((const float4*)(sp + (size_t)(b * LSEQ + t) * SOUT))[tx];
        #pragma unroll
        for (int si = 0; si < 8; si++) {
            float zv = zrow[(size_t)(s0 + si) * LSEQ + t];
            float4 o;
            o.x = fmaf(zv, zw4.x, zb4.x) + sps[si].x * spt.x;
            o.y = fmaf(zv, zw4.y, zb4.y) + sps[si].y * spt.y;
            o.z = fmaf(zv, zw4.z, zb4.z) + sps[si].z * spt.z;
            o.w = fmaf(zv, zw4.w, zb4.w) + sps[si].w * spt.w;
            ((float4*)(orow + ((size_t)(s0 + si) * LSEQ + t) * ZF))[tx] = o;
        }
    }
}

// ---------------- launch ----------------------------------------------------
extern "C" void kernel_launch(void* const* d_in, const int* in_sizes, int n_in,
                              void* d_out, int out_size) {
    const float* s        = (const float*)d_in[0];
    const float* z        = (const float*)d_in[1];
    const float* s_proj_w = (const float*)d_in[2];
    const float* s_proj_b = (const float*)d_in[3];
    const float* z_proj_w = (const float*)d_in[4];
    const float* z_proj_b = (const float*)d_in[5];
    const float* in_proj_w= (const float*)d_in[6];
    const float* conv_w   = (const float*)d_in[7];
    const float* conv_b   = (const float*)d_in[8];
    const float* x_proj_w = (const float*)d_in[9];
    const float* dt_proj_w= (const float*)d_in[10];
    const float* dt_proj_b= (const float*)d_in[11];
    const float* A_log    = (const float*)d_in[12];
    const float* Dp       = (const float*)d_in[13];
    const float* out_proj_w = (const float*)d_in[14];

    float* out    = (float*)d_out;
    float* sp_out = out;                       // [2,768,32]
    float* z_out  = out + (size_t)B_ * LSEQ * SOUT;

    k0_weights<<<(SIN * 128 + 255) / 256, 256>>>(s_proj_w, s_proj_b, in_proj_w);
    k1a_gemm<<<12 * KS, 256>>>(s);
    k1b_reduce<<<NROWS * 128 / 256, 256>>>();
    k2_conv<<<NROWS, 64>>>(conv_w, conv_b, x_proj_w, dt_proj_w, dt_proj_b);
    k4_chunk<<<B_ * NCH, 1024>>>(A_log);
    k5_combine<<<CHAINS / 1024, 1024>>>();
    k6_scan<<<B_ * NCH, 1024>>>(Dp, out_proj_w, sp_out);
    k7_z<<<768, dim3(8, 32)>>>(z, z_proj_w, z_proj_b, sp_out, z_out);
}

// round 3
// speedup vs baseline: 1.4660x; 1.1653x over previous
#include <cuda_runtime.h>

#define B_   2
#define LSEQ 768
#define SIN  1280
#define SOUT 32
#define ZF   32
#define DI   64
#define DS   16
#define NCH  48     // chunks along L
#define CT   16     // chunk length (NCH*CT = LSEQ)
#define NROWS (B_*LSEQ)          // 1536
#define CHAINS (B_*DI*DS)        // 2048
#define KS   10     // split-K factor for K1
#define KC   (SIN/KS)            // 128
#define KT   16     // k sub-tile staged in smem

// ---------------- scratch (device globals; no allocation allowed) ----------
__device__ float g_WcT[SIN*128];        // combined in_proj . s_proj, [i][j]
__device__ float g_bc[128];             // combined bias
__device__ float g_part[KS*NROWS*128];  // split-K partials (7.9 MB)
__device__ float g_xpre[NROWS*DI];      // x before conv
__device__ float g_gate[NROWS*DI];      // gate (raw)
__device__ float g_x[NROWS*DI];         // x after conv+silu
__device__ float g_dt[NROWS*DI];        // softplus(dt)
__device__ float g_Bm[NROWS*DS];
__device__ float g_Cm[NROWS*DS];
__device__ float g_dA[NROWS*1024];      // exp(dt*A)   [t][chain-within-batch]
__device__ float g_dbu[NROWS*1024];     // dt*B*x
__device__ float g_ca[NCH*CHAINS];      // chunk transfer a  ([c][chain], coalesced)
__device__ float g_cb[NCH*CHAINS];      // chunk offset  b
__device__ float g_hi[NCH*CHAINS];      // h at chunk entry

// ---------------- K0: combined weights Wc = in_proj @ s_proj ---------------
__global__ void k0_weights(const float* __restrict__ sw, const float* __restrict__ sb,
                           const float* __restrict__ inw) {
    int idx = blockIdx.x * 256 + threadIdx.x;
    if (idx < SIN * 128) {
        int i = idx >> 7, j = idx & 127;
        float acc = 0.f;
        #pragma unroll
        for (int k = 0; k < SOUT; k++) acc += inw[j*SOUT + k] * sw[k*SIN + i];
        g_WcT[i*128 + j] = acc;
    }
    if (idx < 128) {
        float acc = 0.f;
        #pragma unroll
        for (int k = 0; k < SOUT; k++) acc += inw[idx*SOUT + k] * sb[k];
        g_bc[idx] = acc;
    }
}

// ---------------- K1a: split-K register-tiled GEMM -------------------------
// grid = 12 row-tiles x KS(10) ksplits = 120 blocks (single wave), 256 threads.
// Tile: 128 rows x 128 cols, 8x8 per thread, packed f32x2 FMAs.
__global__ void __launch_bounds__(256) k1a_gemm(const float* __restrict__ s) {
    __shared__ float ss[KT][132];     // [kk][row], padded
    __shared__ float ws2[KT][256];    // [kk][2*j] duplicated weights
    int tid = threadIdx.x;
    int rt = blockIdx.x / KS;
    int ks = blockIdx.x % KS;
    int r0 = rt * 128;
    int kb = ks * KC;
    int tx = tid & 15, ty = tid >> 4;
    int j0 = tx * 8;       // 8 cols per thread
    int row0 = ty * 8;     // 8 rows per thread

    int it0 = tid, it1 = tid + 256;
    int sr0 = it0 >> 2, skg0 = it0 & 3;
    int sr1 = it1 >> 2, skg1 = it1 & 3;
    int wkk0 = it0 >> 5, wjg0 = it0 & 31;
    int wkk1 = it1 >> 5, wjg1 = it1 & 31;

    float4 sv0, sv1, wv0, wv1;
    sv0 = *(const float4*)(s + (size_t)(r0 + sr0)*SIN + kb + skg0*4);
    sv1 = *(const float4*)(s + (size_t)(r0 + sr1)*SIN + kb + skg1*4);
    wv0 = *(const float4*)(g_WcT + (size_t)(kb + wkk0)*128 + wjg0*4);
    wv1 = *(const float4*)(g_WcT + (size_t)(kb + wkk1)*128 + wjg1*4);

    unsigned long long acc[4][8];
    #pragma unroll
    for (int r = 0; r < 4; r++)
        #pragma unroll
        for (int j = 0; j < 8; j++) acc[r][j] = 0ull;

    #pragma unroll 1
    for (int tile = 0; tile < KC/KT; tile++) {
        ss[skg0*4+0][sr0] = sv0.x; ss[skg0*4+1][sr0] = sv0.y;
        ss[skg0*4+2][sr0] = sv0.z; ss[skg0*4+3][sr0] = sv0.w;
        ss[skg1*4+0][sr1] = sv1.x; ss[skg1*4+1][sr1] = sv1.y;
        ss[skg1*4+2][sr1] = sv1.z; ss[skg1*4+3][sr1] = sv1.w;
        *(float4*)&ws2[wkk0][wjg0*8]   = make_float4(wv0.x, wv0.x, wv0.y, wv0.y);
        *(float4*)&ws2[wkk0][wjg0*8+4] = make_float4(wv0.z, wv0.z, wv0.w, wv0.w);
        *(float4*)&ws2[wkk1][wjg1*8]   = make_float4(wv1.x, wv1.x, wv1.y, wv1.y);
        *(float4*)&ws2[wkk1][wjg1*8+4] = make_float4(wv1.z, wv1.z, wv1.w, wv1.w);
        __syncthreads();
        if (tile < KC/KT - 1) {
            int kb2 = kb + (tile+1)*KT;
            sv0 = *(const float4*)(s + (size_t)(r0 + sr0)*SIN + kb2 + skg0*4);
            sv1 = *(const float4*)(s + (size_t)(r0 + sr1)*SIN + kb2 + skg1*4);
            wv0 = *(const float4*)(g_WcT + (size_t)(kb2 + wkk0)*128 + wjg0*4);
            wv1 = *(const float4*)(g_WcT + (size_t)(kb2 + wkk1)*128 + wjg1*4);
        }
        #pragma unroll
        for (int kk = 0; kk < KT; kk++) {
            ulonglong2 sA = *(const ulonglong2*)&ss[kk][row0];
            ulonglong2 sB_ = *(const ulonglong2*)&ss[kk][row0+4];
            ulonglong2 w01 = *(const ulonglong2*)&ws2[kk][j0*2];
            ulonglong2 w23 = *(const ulonglong2*)&ws2[kk][j0*2+4];
            ulonglong2 w45 = *(const ulonglong2*)&ws2[kk][j0*2+8];
            ulonglong2 w67 = *(const ulonglong2*)&ws2[kk][j0*2+12];
            unsigned long long sp[4] = {sA.x, sA.y, sB_.x, sB_.y};
            unsigned long long wd[8] = {w01.x, w01.y, w23.x, w23.y,
                                        w45.x, w45.y, w67.x, w67.y};
            #pragma unroll
            for (int r = 0; r < 4; r++)
                #pragma unroll
                for (int j = 0; j < 8; j++)
                    asm("fma.rn.f32x2 %0, %1, %2, %0;"
                        : "+l"(acc[r][j]) : "l"(sp[r]), "l"(wd[j]));
        }
        __syncthreads();
    }
    #pragma unroll
    for (int rr = 0; rr < 8; rr++) {
        float f[8];
        #pragma unroll
        for (int j = 0; j < 8; j++) {
            float2 q = *(float2*)&acc[rr>>1][j];
            f[j] = (rr & 1) ? q.y : q.x;
        }
        size_t o = ((size_t)ks*NROWS + r0 + row0 + rr)*128 + j0;
        *(float4*)(g_part + o)     = make_float4(f[0], f[1], f[2], f[3]);
        *(float4*)(g_part + o + 4) = make_float4(f[4], f[5], f[6], f[7]);
    }
}

// ---------------- K1b: reduce split-K partials + bias ----------------------
__global__ void __launch_bounds__(256) k1b_reduce() {
    int idx = blockIdx.x * 256 + threadIdx.x;   // < 196608
    float acc = g_bc[idx & 127];
    #pragma unroll
    for (int k = 0; k < KS; k++) acc += g_part[(size_t)k*NROWS*128 + idx];
    int j = idx & 127, row = idx >> 7;
    if (j < DI) g_xpre[row*DI + j] = acc;
    else        g_gate[row*DI + (j - DI)] = acc;
}

// ---------------- K2: conv1d + silu + x_proj + dt (batched, 16 rows/block) --
__global__ void __launch_bounds__(256) k2_conv(const float* __restrict__ convw,
                                               const float* __restrict__ convb,
                                               const float* __restrict__ xpw,
                                               const float* __restrict__ dtw,
                                               const float* __restrict__ dtb) {
    int base = blockIdx.x * 16;          // first row of this block
    int l0 = base % LSEQ;                // position within batch
    int tid = threadIdx.x;
    __shared__ float sxp[19][DI];        // halo rows base-3 .. base+15
    __shared__ float wx[34][65];         // x_proj_w padded
    __shared__ float xs[16][DI];         // conv+silu result
    __shared__ float xd[16][34];
    __shared__ float scwT[4][DI];        // conv weights transposed [k][d]
    __shared__ float scb[DI], sdtw[2*DI], sdtb[DI];

    #pragma unroll
    for (int e = 0; e < 5; e++) {        // 19*64 = 1216 <= 5*256
        int idx = tid + e * 256;
        if (idx < 19 * DI) {
            int i = idx >> 6, d = idx & 63;
            int l = l0 + i - 3;
            sxp[i][d] = (l >= 0) ? g_xpre[(base + i - 3) * DI + d] : 0.f;
        }
    }
    #pragma unroll
    for (int e = 0; e < 9; e++) {        // 34*64 = 2176 <= 9*256
        int idx = tid + e * 256;
        if (idx < 34 * DI) wx[idx >> 6][idx & 63] = xpw[idx];
    }
    scwT[tid & 3][tid >> 2] = convw[tid];                 // 256 = 64*4
    if (tid < DI)       scb[tid]  = convb[tid];
    else if (tid < 3*DI) sdtw[tid - DI] = dtw[tid - DI];  // 128
    else if (tid < 4*DI) sdtb[tid - 3*DI] = dtb[tid - 3*DI];
    __syncthreads();

    #pragma unroll
    for (int e = 0; e < 4; e++) {        // conv + silu: 1024 elems
        int idx = tid + e * 256;
        int r = idx >> 6, d = idx & 63;
        float acc = scb[d];
        #pragma unroll
        for (int kk = 0; kk < 4; kk++) acc = fmaf(sxp[r + kk][d], scwT[kk][d], acc);
        float xv = acc / (1.f + __expf(-acc));
        xs[r][d] = xv;
        g_x[(base + r) * DI + d] = xv;
    }
    __syncthreads();

    if (tid < 544) {                      // x_proj: 16 rows x 34 outs
        int r = tid / 34, j = tid % 34;
        float a = 0.f;
        #pragma unroll
        for (int dd = 0; dd < DI; dd++) a = fmaf(xs[r][dd], wx[j][dd], a);
        xd[r][j] = a;
        if (j >= 18)     g_Cm[(base + r) * DS + (j - 18)] = a;
        else if (j >= 2) g_Bm[(base + r) * DS + (j - 2)]  = a;
    }
    __syncthreads();

    #pragma unroll
    for (int e = 0; e < 4; e++) {        // dt: softplus(dt @ dtw + dtb)
        int idx = tid + e * 256;
        int r = idx >> 6, d = idx & 63;
        float dtraw = fmaf(xd[r][0], sdtw[d * 2],
                      fmaf(xd[r][1], sdtw[d * 2 + 1], sdtb[d]));
        float dtv = fmaxf(dtraw, 0.f) + log1pf(__expf(-fabsf(dtraw)));
        g_dt[(base + r) * DI + d] = dtv;
    }
}

// ---------------- K4: per-chunk scan summaries + materialize dA/dbu --------
__global__ void __launch_bounds__(1024) k4_chunk(const float* __restrict__ A_log) {
    int b = blockIdx.x / NCH, c = blockIdx.x % NCH;
    int tid = threadIdx.x;
    int d = tid >> 4, n = tid & 15;
    __shared__ float sdt[CT][DI], sx[CT][DI], sB[CT][DS];
    int base = b * LSEQ + c * CT;
    { int t = tid >> 6, dd = tid & 63;              // CT*DI == 1024
      sdt[t][dd] = g_dt[(base + t) * DI + dd];
      sx[t][dd]  = g_x[(base + t) * DI + dd]; }
    if (tid < CT * DS) { int t = tid >> 4, nn = tid & 15;
      sB[t][nn] = g_Bm[(base + t) * DS + nn]; }
    __syncthreads();
    float a = -__expf(A_log[d * DS + n]);
    float ra = 1.f, rb = 0.f;
    int chain = b * 1024 + tid;
    #pragma unroll
    for (int t = 0; t < CT; t++) {
        float dtv = sdt[t][d];
        float dA  = __expf(dtv * a);
        float dbu = dtv * sB[t][n] * sx[t][d];
        g_dA [(size_t)(base + t) * 1024 + tid] = dA;
        g_dbu[(size_t)(base + t) * 1024 + tid] = dbu;
        ra *= dA;
        rb = fmaf(dA, rb, dbu);
    }
    g_ca[c * CHAINS + chain] = ra;
    g_cb[c * CHAINS + chain] = rb;
}

// ---------------- K5: combine chunk summaries -> entry states --------------
__global__ void __launch_bounds__(1024) k5_combine() {
    int chain = blockIdx.x * 1024 + threadIdx.x;
    float ca[NCH], cb[NCH];
    #pragma unroll
    for (int c = 0; c < NCH; c++) {
        ca[c] = g_ca[c * CHAINS + chain];
        cb[c] = g_cb[c * CHAINS + chain];
    }
    float h = 0.f;
    #pragma unroll
    for (int c = 0; c < NCH; c++) {
        g_hi[c * CHAINS + chain] = h;
        h = fmaf(ca[c], h, cb[c]);
    }
}

// ---------------- K6: scan pass 2 + D-skip + gate + out_proj ---------------
__global__ void __launch_bounds__(1024) k6_scan(const float* __restrict__ Dp,
                                                const float* __restrict__ opw,
                                                float* __restrict__ out) {
    int b = blockIdx.x / NCH, c = blockIdx.x % NCH;
    int tid = threadIdx.x;
    int d = tid >> 4, n = tid & 15;
    __shared__ float sx[CT][DI], sg[CT][DI], sC[CT][DS];
    __shared__ float ysm[CT][DI];
    __shared__ float sop[SOUT][DI + 1];
    int base = b * LSEQ + c * CT;
    { int t = tid >> 6, dd = tid & 63;
      sx[t][dd] = g_x[(base + t) * DI + dd];
      sg[t][dd] = g_gate[(base + t) * DI + dd]; }
    if (tid < CT * DS) { int t = tid >> 4, nn = tid & 15;
      sC[t][nn] = g_Cm[(base + t) * DS + nn]; }
    for (int idx = tid; idx < SOUT * DI; idx += 1024)
        sop[idx >> 6][idx & 63] = opw[idx];
    float rdA[CT], rdbu[CT];
    #pragma unroll
    for (int t = 0; t < CT; t++) {
        rdA [t] = g_dA [(size_t)(base + t) * 1024 + tid];
        rdbu[t] = g_dbu[(size_t)(base + t) * 1024 + tid];
    }
    int chain = b * 1024 + tid;
    float h  = g_hi[c * CHAINS + chain];
    float Dv = Dp[d];
    __syncthreads();
    #pragma unroll
    for (int t = 0; t < CT; t++) {
        h = fmaf(rdA[t], h, rdbu[t]);
        float cb_ = h * sC[t][n];
        cb_ += __shfl_xor_sync(0xffffffffu, cb_, 8);
        cb_ += __shfl_xor_sync(0xffffffffu, cb_, 4);
        cb_ += __shfl_xor_sync(0xffffffffu, cb_, 2);
        cb_ += __shfl_xor_sync(0xffffffffu, cb_, 1);
        if (n == 0) {
            float y = cb_ + sx[t][d] * Dv;
            float g = sg[t][d];
            y *= g / (1.f + __expf(-g));
            ysm[t][d] = y;
        }
    }
    __syncthreads();
    if (tid < CT * SOUT) {      // 512 threads: 16 t x 32 f
        int t = tid >> 5, f = tid & 31;
        float acc = 0.f;
        #pragma unroll
        for (int dd = 0; dd < DI; dd++) acc = fmaf(ysm[t][dd], sop[f][dd], acc);
        out[(size_t)(base + t) * SOUT + f] = acc;
    }
}

// ---------------- K7: z_prime = z*zw + zb + outer(sp, sp) ------------------
__global__ void __launch_bounds__(256) k7_z(const float* __restrict__ z,
                                            const float* __restrict__ zw,
                                            const float* __restrict__ zbv,
                                            const float* __restrict__ sp,
                                            float* __restrict__ outz) {
    int blk = blockIdx.x;
    int b = blk / 384;
    int rem = blk % 384;
    int s0 = (rem >> 2) * 8;
    int tq = rem & 3;
    int tx = threadIdx.x;   // 0..7  (f/4)
    int ty = threadIdx.y;   // 0..31 (t lane)
    float4 zw4 = ((const float4*)zw)[tx];
    float4 zb4 = ((const float4*)zbv)[tx];
    float4 sps[8];
    #pragma unroll
    for (int si = 0; si < 8; si++)
        sps[si] = ((const float4*)(sp + (size_t)(b * LSEQ + s0 + si) * SOUT))[tx];
    const float* zrow = z + (size_t)(b * LSEQ) * LSEQ;
    float* orow = outz + (size_t)(b * LSEQ) * LSEQ * ZF;
    for (int t0 = tq * 192; t0 < (tq + 1) * 192; t0 += 32) {
        int t = t0 + ty;
        float4 spt = ((const float4*)(sp + (size_t)(b * LSEQ + t) * SOUT))[tx];
        #pragma unroll
        for (int si = 0; si < 8; si++) {
            float zv = zrow[(size_t)(s0 + si) * LSEQ + t];
            float4 o;
            o.x = fmaf(zv, zw4.x, zb4.x) + sps[si].x * spt.x;
            o.y = fmaf(zv, zw4.y, zb4.y) + sps[si].y * spt.y;
            o.z = fmaf(zv, zw4.z, zb4.z) + sps[si].z * spt.z;
            o.w = fmaf(zv, zw4.w, zb4.w) + sps[si].w * spt.w;
            ((float4*)(orow + ((size_t)(s0 + si) * LSEQ + t) * ZF))[tx] = o;
        }
    }
}

// ---------------- launch ----------------------------------------------------
extern "C" void kernel_launch(void* const* d_in, const int* in_sizes, int n_in,
                              void* d_out, int out_size) {
    const float* s        = (const float*)d_in[0];
    const float* z        = (const float*)d_in[1];
    const float* s_proj_w = (const float*)d_in[2];
    const float* s_proj_b = (const float*)d_in[3];
    const float* z_proj_w = (const float*)d_in[4];
    const float* z_proj_b = (const float*)d_in[5];
    const float* in_proj_w= (const float*)d_in[6];
    const float* conv_w   = (const float*)d_in[7];
    const float* conv_b   = (const float*)d_in[8];
    const float* x_proj_w = (const float*)d_in[9];
    const float* dt_proj_w= (const float*)d_in[10];
    const float* dt_proj_b= (const float*)d_in[11];
    const float* A_log    = (const float*)d_in[12];
    const float* Dp       = (const float*)d_in[13];
    const float* out_proj_w = (const float*)d_in[14];

    float* out    = (float*)d_out;
    float* sp_out = out;                       // [2,768,32]
    float* z_out  = out + (size_t)B_ * LSEQ * SOUT;

    k0_weights<<<(SIN * 128 + 255) / 256, 256>>>(s_proj_w, s_proj_b, in_proj_w);
    k1a_gemm<<<12 * KS, 256>>>(s);
    k1b_reduce<<<NROWS * 128 / 256, 256>>>();
    k2_conv<<<NROWS / 16, 256>>>(conv_w, conv_b, x_proj_w, dt_proj_w, dt_proj_b);
    k4_chunk<<<B_ * NCH, 1024>>>(A_log);
    k5_combine<<<CHAINS / 1024, 1024>>>();
    k6_scan<<<B_ * NCH, 1024>>>(Dp, out_proj_w, sp_out);
    k7_z<<<768, dim3(8, 32)>>>(z, z_proj_w, z_proj_b, sp_out, z_out);
}

// round 4
// speedup vs baseline: 1.9185x; 1.3086x over previous
#include <cuda_runtime.h>

#define B_   2
#define LSEQ 768
#define SIN  1280
#define SOUT 32
#define ZF   32
#define DI   64
#define DS   16
#define NCH  48     // chunks along L
#define CT   16     // chunk length
#define NROWS (B_*LSEQ)          // 1536
#define CHAINS (B_*DI*DS)        // 2048
#define KSP  8      // split-K for KA
#define KCA  (SIN/KSP)           // 160

// ---------------- scratch -----------------------------------------------
__device__ float g_part[KSP*NROWS*SOUT];   // KA partials (1.5 MB)
__device__ float g_x[NROWS*DI];            // conv+silu result
__device__ float g_gate[NROWS*DI];
__device__ float g_Cm[NROWS*DS];
__device__ float g_dA[NROWS*1024];
__device__ float g_dbu[NROWS*1024];
__device__ float g_ca[NCH*CHAINS];
__device__ float g_cb[NCH*CHAINS];
__device__ float g_hi[NCH*CHAINS];

// ---------------- KA: s' partials = s @ s_proj^T (split-K) ----------------
// grid = 24 rowtiles x 8 ksplits; block 256. 64 rows x 32 cols per block.
__global__ void __launch_bounds__(256) ka_gemm(const float* __restrict__ s,
                                               const float* __restrict__ spw) {
    __shared__ float sT[32][68];     // [k][row], LDS.128-aligned pad
    __shared__ float wdup[32][64];   // [k][2j] duplicated weights
    int tid = threadIdx.x;
    int rt = blockIdx.x >> 3;
    int ks = blockIdx.x & 7;
    int r0 = rt * 64;
    int kb = ks * KCA;
    int j  = tid & 31;
    int pg = tid >> 5;               // 0..7, rows pg*8..pg*8+7

    unsigned long long acc[4] = {0ull, 0ull, 0ull, 0ull};

    int lrow = tid >> 3;             // 0..31
    int lk4  = (tid & 7) * 4;
    int wj   = tid >> 3;             // 0..31
    int wk4  = (tid & 7) * 4;

    #pragma unroll 1
    for (int tile = 0; tile < KCA / 32; tile++) {
        int ktb = kb + tile * 32;
        __syncthreads();
        // stage s transposed: rows r0..r0+63, k ktb..ktb+31
        #pragma unroll
        for (int half = 0; half < 2; half++) {
            int row = lrow + half * 32;
            float4 v = *(const float4*)(s + (size_t)(r0 + row) * SIN + ktb + lk4);
            sT[lk4 + 0][row] = v.x; sT[lk4 + 1][row] = v.y;
            sT[lk4 + 2][row] = v.z; sT[lk4 + 3][row] = v.w;
        }
        // stage weights duplicated
        {
            float4 w = *(const float4*)(spw + (size_t)wj * SIN + ktb + wk4);
            wdup[wk4 + 0][2 * wj] = w.x; wdup[wk4 + 0][2 * wj + 1] = w.x;
            wdup[wk4 + 1][2 * wj] = w.y; wdup[wk4 + 1][2 * wj + 1] = w.y;
            wdup[wk4 + 2][2 * wj] = w.z; wdup[wk4 + 2][2 * wj + 1] = w.z;
            wdup[wk4 + 3][2 * wj] = w.w; wdup[wk4 + 3][2 * wj + 1] = w.w;
        }
        __syncthreads();
        #pragma unroll
        for (int k = 0; k < 32; k++) {
            ulonglong2 pA = *(const ulonglong2*)&sT[k][pg * 8];      // rows 0-3 (2 pairs)
            ulonglong2 pB = *(const ulonglong2*)&sT[k][pg * 8 + 4];  // rows 4-7
            unsigned long long wv = *(const unsigned long long*)&wdup[k][2 * j];
            asm("fma.rn.f32x2 %0, %1, %2, %0;" : "+l"(acc[0]) : "l"(pA.x), "l"(wv));
            asm("fma.rn.f32x2 %0, %1, %2, %0;" : "+l"(acc[1]) : "l"(pA.y), "l"(wv));
            asm("fma.rn.f32x2 %0, %1, %2, %0;" : "+l"(acc[2]) : "l"(pB.x), "l"(wv));
            asm("fma.rn.f32x2 %0, %1, %2, %0;" : "+l"(acc[3]) : "l"(pB.y), "l"(wv));
        }
    }
    #pragma unroll
    for (int q = 0; q < 4; q++) {
        float2 v = *(float2*)&acc[q];
        int row = r0 + pg * 8 + q * 2;
        g_part[(size_t)ks * NROWS * SOUT + (size_t)row * SOUT + j]       = v.x;
        g_part[(size_t)ks * NROWS * SOUT + (size_t)(row + 1) * SOUT + j] = v.y;
    }
}

// ---------------- KB: fused reduce + in_proj + conv + x_proj + dt + chunk --
// grid = 96 (one per 16-row chunk), block 256.
__global__ void __launch_bounds__(256) kb_fused(const float* __restrict__ spb,
                                                const float* __restrict__ inw,
                                                const float* __restrict__ convw,
                                                const float* __restrict__ convb,
                                                const float* __restrict__ xpw,
                                                const float* __restrict__ dtw,
                                                const float* __restrict__ dtb,
                                                const float* __restrict__ A_log) {
    __shared__ float sps[19][33];     // s' rows base-3..base+15
    __shared__ float winw[128][33];   // in_proj_w padded
    __shared__ float sxpre[19][64];   // x before conv
    __shared__ float sx[16][64];      // x after conv+silu
    __shared__ float xd[16][34];      // x_proj outputs (dt0,dt1,B...)
    __shared__ float sdt[16][64];
    __shared__ float scwT[4][64];
    __shared__ float scb[64], sdtw[128], sdtb[64];

    int tid = threadIdx.x;
    int base = blockIdx.x * 16;
    int b = base / LSEQ;
    int l0 = base % LSEQ;
    int c = l0 / CT;

    // phase 1: reduce partials + bias -> s' (zero for invalid halo rows)
    for (int idx = tid; idx < 19 * SOUT; idx += 256) {
        int row = idx >> 5, jj = idx & 31;
        int grow = base + row - 3;
        float v = 0.f;
        if (l0 != 0 || row >= 3) {
            v = spb[jj];
            #pragma unroll
            for (int ks = 0; ks < KSP; ks++)
                v += g_part[(size_t)ks * NROWS * SOUT + (size_t)grow * SOUT + jj];
        }
        sps[row][jj] = v;
    }
    // stage small weights
    for (int idx = tid; idx < 128 * 32; idx += 256)
        winw[idx >> 5][idx & 31] = inw[idx];
    scwT[tid & 3][tid >> 2] = convw[tid];
    if (tid < 64)        scb[tid] = convb[tid];
    else if (tid < 192)  sdtw[tid - 64] = dtw[tid - 64];
    else                 sdtb[tid - 192] = dtb[tid - 192];
    __syncthreads();

    // phase 2: in_proj GEMM (x part for 19 rows, gate for 16)
    for (int idx = tid; idx < 19 * 64 + 16 * 64; idx += 256) {
        if (idx < 19 * 64) {
            int row = idx >> 6, d = idx & 63;
            float a = 0.f;
            #pragma unroll
            for (int k = 0; k < 32; k++) a = fmaf(sps[row][k], winw[d][k], a);
            sxpre[row][d] = a;
        } else {
            int i2 = idx - 19 * 64;
            int row = i2 >> 6, d = i2 & 63;
            float a = 0.f;
            #pragma unroll
            for (int k = 0; k < 32; k++) a = fmaf(sps[row + 3][k], winw[64 + d][k], a);
            g_gate[(base + row) * DI + d] = a;
        }
    }
    __syncthreads();

    // phase 3: conv + silu
    #pragma unroll
    for (int e = 0; e < 4; e++) {
        int idx = tid + e * 256;
        int r = idx >> 6, d = idx & 63;
        float acc = scb[d];
        #pragma unroll
        for (int kk = 0; kk < 4; kk++) acc = fmaf(sxpre[r + kk][d], scwT[kk][d], acc);
        float xv = acc / (1.f + __expf(-acc));
        sx[r][d] = xv;
        g_x[(base + r) * DI + d] = xv;
    }
    __syncthreads();

    // phase 4: x_proj (34 outputs per row)
    if (tid < 544) {
        int r = tid / 34, jj = tid % 34;
        float a = 0.f;
        #pragma unroll
        for (int dd = 0; dd < 64; dd++) a = fmaf(sx[r][dd], xpw[jj * 64 + dd], a);
        xd[r][jj] = a;
        if (jj >= 18) g_Cm[(base + r) * DS + (jj - 18)] = a;
    }
    __syncthreads();

    // phase 5: dt = softplus(dt_pre @ dtw + dtb)
    #pragma unroll
    for (int e = 0; e < 4; e++) {
        int idx = tid + e * 256;
        int r = idx >> 6, d = idx & 63;
        float dtraw = fmaf(xd[r][0], sdtw[d * 2],
                      fmaf(xd[r][1], sdtw[d * 2 + 1], sdtb[d]));
        sdt[r][d] = fmaxf(dtraw, 0.f) + log1pf(__expf(-fabsf(dtraw)));
    }
    __syncthreads();

    // phase 6: chunk scan (4 chains per thread: chain = tid*4+q)
    {
        int d = tid >> 2;
        int nq0 = (tid & 3) * 4;
        float4 al = *(const float4*)(A_log + d * DS + nq0);
        float a0 = -__expf(al.x), a1 = -__expf(al.y);
        float a2 = -__expf(al.z), a3 = -__expf(al.w);
        float ra0 = 1.f, ra1 = 1.f, ra2 = 1.f, ra3 = 1.f;
        float rb0 = 0.f, rb1 = 0.f, rb2 = 0.f, rb3 = 0.f;
        #pragma unroll
        for (int t = 0; t < CT; t++) {
            float dtv = sdt[t][d];
            float xv  = sx[t][d];
            float dtx = dtv * xv;
            float B0 = xd[t][2 + nq0], B1 = xd[t][3 + nq0];
            float B2 = xd[t][4 + nq0], B3 = xd[t][5 + nq0];
            float dA0 = __expf(dtv * a0), dA1 = __expf(dtv * a1);
            float dA2 = __expf(dtv * a2), dA3 = __expf(dtv * a3);
            float db0 = dtx * B0, db1 = dtx * B1, db2 = dtx * B2, db3 = dtx * B3;
            size_t o = (size_t)(base + t) * 1024 + tid * 4;
            *(float4*)(g_dA + o)  = make_float4(dA0, dA1, dA2, dA3);
            *(float4*)(g_dbu + o) = make_float4(db0, db1, db2, db3);
            ra0 *= dA0; ra1 *= dA1; ra2 *= dA2; ra3 *= dA3;
            rb0 = fmaf(dA0, rb0, db0); rb1 = fmaf(dA1, rb1, db1);
            rb2 = fmaf(dA2, rb2, db2); rb3 = fmaf(dA3, rb3, db3);
        }
        size_t o = (size_t)c * CHAINS + b * 1024 + tid * 4;
        *(float4*)(g_ca + o) = make_float4(ra0, ra1, ra2, ra3);
        *(float4*)(g_cb + o) = make_float4(rb0, rb1, rb2, rb3);
    }
}

// ---------------- K5: combine chunk summaries -> entry states --------------
__global__ void __launch_bounds__(1024) k5_combine() {
    int chain = blockIdx.x * 1024 + threadIdx.x;
    float ca[NCH], cb[NCH];
    #pragma unroll
    for (int c = 0; c < NCH; c++) {
        ca[c] = g_ca[c * CHAINS + chain];
        cb[c] = g_cb[c * CHAINS + chain];
    }
    float h = 0.f;
    #pragma unroll
    for (int c = 0; c < NCH; c++) {
        g_hi[c * CHAINS + chain] = h;
        h = fmaf(ca[c], h, cb[c]);
    }
}

// ---------------- K6: scan pass 2 + D-skip + gate + out_proj ---------------
__global__ void __launch_bounds__(1024) k6_scan(const float* __restrict__ Dp,
                                                const float* __restrict__ opw,
                                                float* __restrict__ out) {
    int b = blockIdx.x / NCH, c = blockIdx.x % NCH;
    int tid = threadIdx.x;
    int d = tid >> 4, n = tid & 15;
    __shared__ float sx[CT][DI], sg[CT][DI], sC[CT][DS];
    __shared__ float ysm[CT][DI];
    __shared__ float sop[SOUT][DI + 1];
    int base = b * LSEQ + c * CT;
    { int t = tid >> 6, dd = tid & 63;
      sx[t][dd] = g_x[(base + t) * DI + dd];
      sg[t][dd] = g_gate[(base + t) * DI + dd]; }
    if (tid < CT * DS) { int t = tid >> 4, nn = tid & 15;
      sC[t][nn] = g_Cm[(base + t) * DS + nn]; }
    for (int idx = tid; idx < SOUT * DI; idx += 1024)
        sop[idx >> 6][idx & 63] = opw[idx];
    float rdA[CT], rdbu[CT];
    #pragma unroll
    for (int t = 0; t < CT; t++) {
        rdA [t] = g_dA [(size_t)(base + t) * 1024 + tid];
        rdbu[t] = g_dbu[(size_t)(base + t) * 1024 + tid];
    }
    int chain = b * 1024 + tid;
    float h  = g_hi[c * CHAINS + chain];
    float Dv = Dp[d];
    __syncthreads();
    #pragma unroll
    for (int t = 0; t < CT; t++) {
        h = fmaf(rdA[t], h, rdbu[t]);
        float cb_ = h * sC[t][n];
        cb_ += __shfl_xor_sync(0xffffffffu, cb_, 8);
        cb_ += __shfl_xor_sync(0xffffffffu, cb_, 4);
        cb_ += __shfl_xor_sync(0xffffffffu, cb_, 2);
        cb_ += __shfl_xor_sync(0xffffffffu, cb_, 1);
        if (n == 0) {
            float y = cb_ + sx[t][d] * Dv;
            float g = sg[t][d];
            y *= g / (1.f + __expf(-g));
            ysm[t][d] = y;
        }
    }
    __syncthreads();
    if (tid < CT * SOUT) {
        int t = tid >> 5, f = tid & 31;
        float acc = 0.f;
        #pragma unroll
        for (int dd = 0; dd < DI; dd++) acc = fmaf(ysm[t][dd], sop[f][dd], acc);
        out[(size_t)(base + t) * SOUT + f] = acc;
    }
}

// ---------------- K7: z_prime = z*zw + zb + outer(sp, sp) ------------------
__global__ void __launch_bounds__(256) k7_z(const float* __restrict__ z,
                                            const float* __restrict__ zw,
                                            const float* __restrict__ zbv,
                                            const float* __restrict__ sp,
                                            float* __restrict__ outz) {
    int blk = blockIdx.x;
    int b = blk / 384;
    int rem = blk % 384;
    int s0 = (rem >> 2) * 8;
    int tq = rem & 3;
    int tx = threadIdx.x;   // 0..7  (f/4)
    int ty = threadIdx.y;   // 0..31
    float4 zw4 = ((const float4*)zw)[tx];
    float4 zb4 = ((const float4*)zbv)[tx];
    float4 sps[8];
    #pragma unroll
    for (int si = 0; si < 8; si++)
        sps[si] = ((const float4*)(sp + (size_t)(b * LSEQ + s0 + si) * SOUT))[tx];
    const float* zrow = z + (size_t)(b * LSEQ) * LSEQ;
    float* orow = outz + (size_t)(b * LSEQ) * LSEQ * ZF;
    for (int t0 = tq * 192; t0 < (tq + 1) * 192; t0 += 32) {
        int t = t0 + ty;
        float4 spt = ((const float4*)(sp + (size_t)(b * LSEQ + t) * SOUT))[tx];
        #pragma unroll
        for (int si = 0; si < 8; si++) {
            float zv = zrow[(size_t)(s0 + si) * LSEQ + t];
            float4 o;
            o.x = fmaf(zv, zw4.x, zb4.x) + sps[si].x * spt.x;
            o.y = fmaf(zv, zw4.y, zb4.y) + sps[si].y * spt.y;
            o.z = fmaf(zv, zw4.z, zb4.z) + sps[si].z * spt.z;
            o.w = fmaf(zv, zw4.w, zb4.w) + sps[si].w * spt.w;
            ((float4*)(orow + ((size_t)(s0 + si) * LSEQ + t) * ZF))[tx] = o;
        }
    }
}

// ---------------- launch ----------------------------------------------------
extern "C" void kernel_launch(void* const* d_in, const int* in_sizes, int n_in,
                              void* d_out, int out_size) {
    const float* s        = (const float*)d_in[0];
    const float* z        = (const float*)d_in[1];
    const float* s_proj_w = (const float*)d_in[2];
    const float* s_proj_b = (const float*)d_in[3];
    const float* z_proj_w = (const float*)d_in[4];
    const float* z_proj_b = (const float*)d_in[5];
    const float* in_proj_w= (const float*)d_in[6];
    const float* conv_w   = (const float*)d_in[7];
    const float* conv_b   = (const float*)d_in[8];
    const float* x_proj_w = (const float*)d_in[9];
    const float* dt_proj_w= (const float*)d_in[10];
    const float* dt_proj_b= (const float*)d_in[11];
    const float* A_log    = (const float*)d_in[12];
    const float* Dp       = (const float*)d_in[13];
    const float* out_proj_w = (const float*)d_in[14];

    float* out    = (float*)d_out;
    float* sp_out = out;                       // [2,768,32]
    float* z_out  = out + (size_t)B_ * LSEQ * SOUT;

    ka_gemm<<<24 * KSP, 256>>>(s, s_proj_w);
    kb_fused<<<NROWS / 16, 256>>>(s_proj_b, in_proj_w, conv_w, conv_b,
                                  x_proj_w, dt_proj_w, dt_proj_b, A_log);
    k5_combine<<<CHAINS / 1024, 1024>>>();
    k6_scan<<<B_ * NCH, 1024>>>(Dp, out_proj_w, sp_out);
    k7_z<<<768, dim3(8, 32)>>>(z, z_proj_w, z_proj_b, sp_out, z_out);
}

// round 5
// speedup vs baseline: 2.4420x; 1.2729x over previous
#include <cuda_runtime.h>

#define B_   2
#define LSEQ 768
#define SIN  1280
#define SOUT 32
#define ZF   32
#define DI   64
#define DS   16
#define NCH  48     // chunks along L
#define CT   16     // chunk length
#define NROWS (B_*LSEQ)          // 1536
#define CHAINS (B_*DI*DS)        // 2048
#define KSP  8      // split-K for KA
#define KCA  (SIN/KSP)           // 160

// ---------------- scratch -----------------------------------------------
__device__ float g_part[KSP*NROWS*SOUT];   // KA partials (1.5 MB)
__device__ float g_x[NROWS*DI];            // conv+silu result
__device__ float g_gate[NROWS*DI];
__device__ float g_dt[NROWS*DI];
__device__ float g_Bm[NROWS*DS];
__device__ float g_Cm[NROWS*DS];
__device__ float g_ca[NCH*CHAINS];
__device__ float g_cb[NCH*CHAINS];
__device__ float g_hi[NCH*CHAINS];

// ---------------- KA: s' partials = s @ s_proj^T (split-K) ----------------
__global__ void __launch_bounds__(256) ka_gemm(const float* __restrict__ s,
                                               const float* __restrict__ spw) {
    __shared__ float sT[32][68];
    __shared__ float wdup[32][64];
    int tid = threadIdx.x;
    int rt = blockIdx.x >> 3;
    int ks = blockIdx.x & 7;
    int r0 = rt * 64;
    int kb = ks * KCA;
    int j  = tid & 31;
    int pg = tid >> 5;

    unsigned long long acc[4] = {0ull, 0ull, 0ull, 0ull};

    int lrow = tid >> 3;
    int lk4  = (tid & 7) * 4;
    int wj   = tid >> 3;
    int wk4  = (tid & 7) * 4;

    #pragma unroll 1
    for (int tile = 0; tile < KCA / 32; tile++) {
        int ktb = kb + tile * 32;
        __syncthreads();
        #pragma unroll
        for (int half = 0; half < 2; half++) {
            int row = lrow + half * 32;
            float4 v = *(const float4*)(s + (size_t)(r0 + row) * SIN + ktb + lk4);
            sT[lk4 + 0][row] = v.x; sT[lk4 + 1][row] = v.y;
            sT[lk4 + 2][row] = v.z; sT[lk4 + 3][row] = v.w;
        }
        {
            float4 w = *(const float4*)(spw + (size_t)wj * SIN + ktb + wk4);
            wdup[wk4 + 0][2 * wj] = w.x; wdup[wk4 + 0][2 * wj + 1] = w.x;
            wdup[wk4 + 1][2 * wj] = w.y; wdup[wk4 + 1][2 * wj + 1] = w.y;
            wdup[wk4 + 2][2 * wj] = w.z; wdup[wk4 + 2][2 * wj + 1] = w.z;
            wdup[wk4 + 3][2 * wj] = w.w; wdup[wk4 + 3][2 * wj + 1] = w.w;
        }
        __syncthreads();
        #pragma unroll
        for (int k = 0; k < 32; k++) {
            ulonglong2 pA = *(const ulonglong2*)&sT[k][pg * 8];
            ulonglong2 pB = *(const ulonglong2*)&sT[k][pg * 8 + 4];
            unsigned long long wv = *(const unsigned long long*)&wdup[k][2 * j];
            asm("fma.rn.f32x2 %0, %1, %2, %0;" : "+l"(acc[0]) : "l"(pA.x), "l"(wv));
            asm("fma.rn.f32x2 %0, %1, %2, %0;" : "+l"(acc[1]) : "l"(pA.y), "l"(wv));
            asm("fma.rn.f32x2 %0, %1, %2, %0;" : "+l"(acc[2]) : "l"(pB.x), "l"(wv));
            asm("fma.rn.f32x2 %0, %1, %2, %0;" : "+l"(acc[3]) : "l"(pB.y), "l"(wv));
        }
    }
    #pragma unroll
    for (int q = 0; q < 4; q++) {
        float2 v = *(float2*)&acc[q];
        int row = r0 + pg * 8 + q * 2;
        g_part[(size_t)ks * NROWS * SOUT + (size_t)row * SOUT + j]       = v.x;
        g_part[(size_t)ks * NROWS * SOUT + (size_t)(row + 1) * SOUT + j] = v.y;
    }
}

// ---------------- KB: fused reduce + in_proj + conv + x_proj + dt + chunk --
// grid = 96 (one per 16-row chunk), block 512.
__global__ void __launch_bounds__(512) kb_fused(const float* __restrict__ spb,
                                                const float* __restrict__ inw,
                                                const float* __restrict__ convw,
                                                const float* __restrict__ convb,
                                                const float* __restrict__ xpw,
                                                const float* __restrict__ dtw,
                                                const float* __restrict__ dtb,
                                                const float* __restrict__ A_log) {
    __shared__ float sps[19][33];
    __shared__ float winw[128][33];
    __shared__ float sxpre[19][64];
    __shared__ float sx[16][64];
    __shared__ float xd[16][34];
    __shared__ float sdt[16][64];
    __shared__ float scwT[4][64];
    __shared__ float scb[64], sdtw[128], sdtb[64];

    int tid = threadIdx.x;
    int base = blockIdx.x * 16;
    int b = base / LSEQ;
    int l0 = base % LSEQ;
    int c = l0 / CT;

    // phase 1: reduce partials + bias -> s' (zero for invalid halo rows)
    for (int idx = tid; idx < 19 * SOUT; idx += 512) {
        int row = idx >> 5, jj = idx & 31;
        int grow = base + row - 3;
        float v = 0.f;
        if (l0 != 0 || row >= 3) {
            v = spb[jj];
            #pragma unroll
            for (int ks = 0; ks < KSP; ks++)
                v += g_part[(size_t)ks * NROWS * SOUT + (size_t)grow * SOUT + jj];
        }
        sps[row][jj] = v;
    }
    for (int idx = tid; idx < 128 * 32; idx += 512)
        winw[idx >> 5][idx & 31] = inw[idx];
    if (tid < 256)        scwT[tid & 3][tid >> 2] = convw[tid];
    else if (tid < 320)   scb[tid - 256] = convb[tid - 256];
    else if (tid < 448)   sdtw[tid - 320] = dtw[tid - 320];
    else                  sdtb[tid - 448] = dtb[tid - 448];
    __syncthreads();

    // phase 2: in_proj GEMM
    for (int idx = tid; idx < 19 * 64 + 16 * 64; idx += 512) {
        if (idx < 19 * 64) {
            int row = idx >> 6, d = idx & 63;
            float a = 0.f;
            #pragma unroll
            for (int k = 0; k < 32; k++) a = fmaf(sps[row][k], winw[d][k], a);
            sxpre[row][d] = a;
        } else {
            int i2 = idx - 19 * 64;
            int row = i2 >> 6, d = i2 & 63;
            float a = 0.f;
            #pragma unroll
            for (int k = 0; k < 32; k++) a = fmaf(sps[row + 3][k], winw[64 + d][k], a);
            g_gate[(base + row) * DI + d] = a;
        }
    }
    __syncthreads();

    // phase 3: conv + silu
    for (int idx = tid; idx < 1024; idx += 512) {
        int r = idx >> 6, d = idx & 63;
        float acc = scb[d];
        #pragma unroll
        for (int kk = 0; kk < 4; kk++) acc = fmaf(sxpre[r + kk][d], scwT[kk][d], acc);
        float xv = acc / (1.f + __expf(-acc));
        sx[r][d] = xv;
        g_x[(base + r) * DI + d] = xv;
    }
    __syncthreads();

    // phase 4: x_proj
    for (int idx = tid; idx < 544; idx += 512) {
        int r = idx / 34, jj = idx % 34;
        float a = 0.f;
        #pragma unroll
        for (int dd = 0; dd < 64; dd++) a = fmaf(sx[r][dd], xpw[jj * 64 + dd], a);
        xd[r][jj] = a;
        if (jj >= 18)      g_Cm[(base + r) * DS + (jj - 18)] = a;
        else if (jj >= 2)  g_Bm[(base + r) * DS + (jj - 2)]  = a;
    }
    __syncthreads();

    // phase 5: dt = softplus(...)
    for (int idx = tid; idx < 1024; idx += 512) {
        int r = idx >> 6, d = idx & 63;
        float dtraw = fmaf(xd[r][0], sdtw[d * 2],
                      fmaf(xd[r][1], sdtw[d * 2 + 1], sdtb[d]));
        float dtv = fmaxf(dtraw, 0.f) + log1pf(__expf(-fabsf(dtraw)));
        sdt[r][d] = dtv;
        g_dt[(base + r) * DI + d] = dtv;
    }
    __syncthreads();

    // phase 6: chunk scan summaries (2 chains per thread)
    {
        int d = tid >> 3;
        int n0 = (tid & 7) * 2;
        float2 al = *(const float2*)(A_log + d * DS + n0);
        float a0 = -__expf(al.x), a1 = -__expf(al.y);
        float ra0 = 1.f, ra1 = 1.f, rb0 = 0.f, rb1 = 0.f;
        #pragma unroll
        for (int t = 0; t < CT; t++) {
            float dtv = sdt[t][d];
            float dtx = dtv * sx[t][d];
            float B0 = xd[t][2 + n0], B1 = xd[t][3 + n0];
            float dA0 = __expf(dtv * a0), dA1 = __expf(dtv * a1);
            ra0 *= dA0; ra1 *= dA1;
            rb0 = fmaf(dA0, rb0, dtx * B0);
            rb1 = fmaf(dA1, rb1, dtx * B1);
        }
        size_t o = (size_t)c * CHAINS + b * 1024 + tid * 2;
        *(float2*)(g_ca + o) = make_float2(ra0, ra1);
        *(float2*)(g_cb + o) = make_float2(rb0, rb1);
    }
}

// ---------------- K5: combine chunk summaries -> entry states --------------
__global__ void __launch_bounds__(1024) k5_combine() {
    int chain = blockIdx.x * 1024 + threadIdx.x;
    float ca[NCH], cb[NCH];
    #pragma unroll
    for (int c = 0; c < NCH; c++) {
        ca[c] = g_ca[c * CHAINS + chain];
        cb[c] = g_cb[c * CHAINS + chain];
    }
    float h = 0.f;
    #pragma unroll
    for (int c = 0; c < NCH; c++) {
        g_hi[c * CHAINS + chain] = h;
        h = fmaf(ca[c], h, cb[c]);
    }
}

// ---------------- K6: scan pass 2 (recomputes dA/dbu) + gate + out_proj ----
__global__ void __launch_bounds__(1024) k6_scan(const float* __restrict__ A_log,
                                                const float* __restrict__ Dp,
                                                const float* __restrict__ opw,
                                                float* __restrict__ out) {
    int b = blockIdx.x / NCH, c = blockIdx.x % NCH;
    int tid = threadIdx.x;
    int d = tid >> 4, n = tid & 15;
    __shared__ float sx[CT][DI], sg[CT][DI], sdt[CT][DI];
    __shared__ float sB[CT][DS], sC[CT][DS];
    __shared__ float ysm[CT][DI];
    __shared__ float sop[SOUT][DI + 1];
    int base = b * LSEQ + c * CT;
    { int t = tid >> 6, dd = tid & 63;
      sx[t][dd]  = g_x[(base + t) * DI + dd];
      sg[t][dd]  = g_gate[(base + t) * DI + dd];
      sdt[t][dd] = g_dt[(base + t) * DI + dd]; }
    if (tid < CT * DS) { int t = tid >> 4, nn = tid & 15;
      sB[t][nn] = g_Bm[(base + t) * DS + nn];
      sC[t][nn] = g_Cm[(base + t) * DS + nn]; }
    for (int idx = tid; idx < SOUT * DI; idx += 1024)
        sop[idx >> 6][idx & 63] = opw[idx];
    float a = -__expf(A_log[tid]);
    float h = g_hi[c * CHAINS + b * 1024 + tid];
    float Dv = Dp[d];
    __syncthreads();
    #pragma unroll
    for (int t = 0; t < CT; t++) {
        float dtv = sdt[t][d];
        float dA  = __expf(dtv * a);
        float dbu = dtv * sB[t][n] * sx[t][d];
        h = fmaf(dA, h, dbu);
        float cb_ = h * sC[t][n];
        cb_ += __shfl_xor_sync(0xffffffffu, cb_, 8);
        cb_ += __shfl_xor_sync(0xffffffffu, cb_, 4);
        cb_ += __shfl_xor_sync(0xffffffffu, cb_, 2);
        cb_ += __shfl_xor_sync(0xffffffffu, cb_, 1);
        if (n == 0) {
            float y = cb_ + sx[t][d] * Dv;
            float g = sg[t][d];
            y *= g / (1.f + __expf(-g));
            ysm[t][d] = y;
        }
    }
    __syncthreads();
    if (tid < CT * SOUT) {
        int t = tid >> 5, f = tid & 31;
        float acc = 0.f;
        #pragma unroll
        for (int dd = 0; dd < DI; dd++) acc = fmaf(ysm[t][dd], sop[f][dd], acc);
        out[(size_t)(base + t) * SOUT + f] = acc;
    }
}

// ---------------- K7: z_prime = z*zw + zb + outer(sp, sp) ------------------
// grid = B_ x 96 sgroups x 2 t-halves = 384 blocks; block (8,32).
#define STG_CS_V4(ptr, vx, vy, vz, vw) \
    asm volatile("st.global.cs.v4.f32 [%0], {%1,%2,%3,%4};" \
                 :: "l"(ptr), "f"(vx), "f"(vy), "f"(vz), "f"(vw) : "memory")

__global__ void __launch_bounds__(256) k7_z(const float* __restrict__ z,
                                            const float* __restrict__ zw,
                                            const float* __restrict__ zbv,
                                            const float* __restrict__ sp,
                                            float* __restrict__ outz) {
    int blk = blockIdx.x;
    int b = blk / 192;
    int rem = blk % 192;
    int s0 = (rem >> 1) * 8;
    int th = rem & 1;
    int tx = threadIdx.x;   // 0..7  (f/4)
    int ty = threadIdx.y;   // 0..31
    float4 zw4 = ((const float4*)zw)[tx];
    float4 zb4 = ((const float4*)zbv)[tx];
    float4 sps[8];
    #pragma unroll
    for (int si = 0; si < 8; si++)
        sps[si] = ((const float4*)(sp + (size_t)(b * LSEQ + s0 + si) * SOUT))[tx];
    const float* zrow = z + (size_t)(b * LSEQ) * LSEQ;
    float* orow = outz + (size_t)(b * LSEQ) * LSEQ * ZF;

    for (int t0 = th * 384; t0 < th * 384 + 384; t0 += 128) {
        int tb = t0 + ty * 4;
        float4 spt[4];
        #pragma unroll
        for (int j = 0; j < 4; j++)
            spt[j] = ((const float4*)(sp + (size_t)(b * LSEQ + tb + j) * SOUT))[tx];
        #pragma unroll
        for (int si = 0; si < 8; si++) {
            float4 zq = *(const float4*)(zrow + (size_t)(s0 + si) * LSEQ + tb);
            float zvals[4] = {zq.x, zq.y, zq.z, zq.w};
            #pragma unroll
            for (int j = 0; j < 4; j++) {
                float zv = zvals[j];
                float ox = fmaf(zv, zw4.x, zb4.x) + sps[si].x * spt[j].x;
                float oy = fmaf(zv, zw4.y, zb4.y) + sps[si].y * spt[j].y;
                float oz = fmaf(zv, zw4.z, zb4.z) + sps[si].z * spt[j].z;
                float ow = fmaf(zv, zw4.w, zb4.w) + sps[si].w * spt[j].w;
                float* p = orow + ((size_t)(s0 + si) * LSEQ + tb + j) * ZF + tx * 4;
                STG_CS_V4(p, ox, oy, oz, ow);
            }
        }
    }
}

// ---------------- launch ----------------------------------------------------
extern "C" void kernel_launch(void* const* d_in, const int* in_sizes, int n_in,
                              void* d_out, int out_size) {
    const float* s        = (const float*)d_in[0];
    const float* z        = (const float*)d_in[1];
    const float* s_proj_w = (const float*)d_in[2];
    const float* s_proj_b = (const float*)d_in[3];
    const float* z_proj_w = (const float*)d_in[4];
    const float* z_proj_b = (const float*)d_in[5];
    const float* in_proj_w= (const float*)d_in[6];
    const float* conv_w   = (const float*)d_in[7];
    const float* conv_b   = (const float*)d_in[8];
    const float* x_proj_w = (const float*)d_in[9];
    const float* dt_proj_w= (const float*)d_in[10];
    const float* dt_proj_b= (const float*)d_in[11];
    const float* A_log    = (const float*)d_in[12];
    const float* Dp       = (const float*)d_in[13];
    const float* out_proj_w = (const float*)d_in[14];

    float* out    = (float*)d_out;
    float* sp_out = out;                       // [2,768,32]
    float* z_out  = out + (size_t)B_ * LSEQ * SOUT;

    ka_gemm<<<24 * KSP, 256>>>(s, s_proj_w);
    kb_fused<<<NROWS / 16, 512>>>(s_proj_b, in_proj_w, conv_w, conv_b,
                                  x_proj_w, dt_proj_w, dt_proj_b, A_log);
    k5_combine<<<CHAINS / 1024, 1024>>>();
    k6_scan<<<B_ * NCH, 1024>>>(A_log, Dp, out_proj_w, sp_out);
    k7_z<<<384, dim3(8, 32)>>>(z, z_proj_w, z_proj_b, sp_out, z_out);
}

// round 6
// speedup vs baseline: 2.5593x; 1.0480x over previous
#include <cuda_runtime.h>

#define B_   2
#define LSEQ 768
#define SIN  1280
#define SOUT 32
#define ZF   32
#define DI   64
#define DS   16
#define NCH  96     // sub-chunks along L
#define CT   8      // sub-chunk length
#define NROWS (B_*LSEQ)          // 1536
#define CHAINS (B_*DI*DS)        // 2048
#define KSP  8      // split-K for KA
#define KCA  (SIN/KSP)           // 160

// ---------------- scratch -----------------------------------------------
__device__ float g_part[KSP*NROWS*SOUT];   // KA partials (1.5 MB)
__device__ float g_x[NROWS*DI];            // conv+silu result
__device__ float g_gate[NROWS*DI];
__device__ float g_dt[NROWS*DI];
__device__ float g_Bm[NROWS*DS];
__device__ float g_Cm[NROWS*DS];
__device__ float g_ca[NCH*CHAINS];
__device__ float g_cb[NCH*CHAINS];
__device__ float g_hi[NCH*CHAINS];

// ---------------- KA: s' partials = s @ s_proj^T (split-K) ----------------
__global__ void __launch_bounds__(256) ka_gemm(const float* __restrict__ s,
                                               const float* __restrict__ spw) {
    __shared__ float sT[32][68];
    __shared__ float wdup[32][64];
    int tid = threadIdx.x;
    int rt = blockIdx.x >> 3;
    int ks = blockIdx.x & 7;
    int r0 = rt * 64;
    int kb = ks * KCA;
    int j  = tid & 31;
    int pg = tid >> 5;

    unsigned long long acc[4] = {0ull, 0ull, 0ull, 0ull};

    int lrow = tid >> 3;
    int lk4  = (tid & 7) * 4;
    int wj   = tid >> 3;
    int wk4  = (tid & 7) * 4;

    #pragma unroll 1
    for (int tile = 0; tile < KCA / 32; tile++) {
        int ktb = kb + tile * 32;
        __syncthreads();
        #pragma unroll
        for (int half = 0; half < 2; half++) {
            int row = lrow + half * 32;
            float4 v = *(const float4*)(s + (size_t)(r0 + row) * SIN + ktb + lk4);
            sT[lk4 + 0][row] = v.x; sT[lk4 + 1][row] = v.y;
            sT[lk4 + 2][row] = v.z; sT[lk4 + 3][row] = v.w;
        }
        {
            float4 w = *(const float4*)(spw + (size_t)wj * SIN + ktb + wk4);
            wdup[wk4 + 0][2 * wj] = w.x; wdup[wk4 + 0][2 * wj + 1] = w.x;
            wdup[wk4 + 1][2 * wj] = w.y; wdup[wk4 + 1][2 * wj + 1] = w.y;
            wdup[wk4 + 2][2 * wj] = w.z; wdup[wk4 + 2][2 * wj + 1] = w.z;
            wdup[wk4 + 3][2 * wj] = w.w; wdup[wk4 + 3][2 * wj + 1] = w.w;
        }
        __syncthreads();
        #pragma unroll
        for (int k = 0; k < 32; k++) {
            ulonglong2 pA = *(const ulonglong2*)&sT[k][pg * 8];
            ulonglong2 pB = *(const ulonglong2*)&sT[k][pg * 8 + 4];
            unsigned long long wv = *(const unsigned long long*)&wdup[k][2 * j];
            asm("fma.rn.f32x2 %0, %1, %2, %0;" : "+l"(acc[0]) : "l"(pA.x), "l"(wv));
            asm("fma.rn.f32x2 %0, %1, %2, %0;" : "+l"(acc[1]) : "l"(pA.y), "l"(wv));
            asm("fma.rn.f32x2 %0, %1, %2, %0;" : "+l"(acc[2]) : "l"(pB.x), "l"(wv));
            asm("fma.rn.f32x2 %0, %1, %2, %0;" : "+l"(acc[3]) : "l"(pB.y), "l"(wv));
        }
    }
    #pragma unroll
    for (int q = 0; q < 4; q++) {
        float2 v = *(float2*)&acc[q];
        int row = r0 + pg * 8 + q * 2;
        g_part[(size_t)ks * NROWS * SOUT + (size_t)row * SOUT + j]       = v.x;
        g_part[(size_t)ks * NROWS * SOUT + (size_t)(row + 1) * SOUT + j] = v.y;
    }
}

// ---------------- KB: fused reduce + in_proj + conv + x_proj + dt + chunk --
// grid = 96 (one per 16-row block), block 512. Emits TWO 8-t sub-chunk summaries.
__global__ void __launch_bounds__(512) kb_fused(const float* __restrict__ spb,
                                                const float* __restrict__ inw,
                                                const float* __restrict__ convw,
                                                const float* __restrict__ convb,
                                                const float* __restrict__ xpw,
                                                const float* __restrict__ dtw,
                                                const float* __restrict__ dtb,
                                                const float* __restrict__ A_log) {
    __shared__ float sps[19][33];
    __shared__ float winw[128][33];
    __shared__ float sxpre[19][64];
    __shared__ float sx[16][64];
    __shared__ float xd[16][34];
    __shared__ float sdt[16][64];
    __shared__ float scwT[4][64];
    __shared__ float scb[64], sdtw[128], sdtb[64];

    int tid = threadIdx.x;
    int base = blockIdx.x * 16;
    int b = base / LSEQ;
    int l0 = base % LSEQ;

    for (int idx = tid; idx < 19 * SOUT; idx += 512) {
        int row = idx >> 5, jj = idx & 31;
        int grow = base + row - 3;
        float v = 0.f;
        if (l0 != 0 || row >= 3) {
            v = spb[jj];
            #pragma unroll
            for (int ks = 0; ks < KSP; ks++)
                v += g_part[(size_t)ks * NROWS * SOUT + (size_t)grow * SOUT + jj];
        }
        sps[row][jj] = v;
    }
    for (int idx = tid; idx < 128 * 32; idx += 512)
        winw[idx >> 5][idx & 31] = inw[idx];
    if (tid < 256)        scwT[tid & 3][tid >> 2] = convw[tid];
    else if (tid < 320)   scb[tid - 256] = convb[tid - 256];
    else if (tid < 448)   sdtw[tid - 320] = dtw[tid - 320];
    else                  sdtb[tid - 448] = dtb[tid - 448];
    __syncthreads();

    for (int idx = tid; idx < 19 * 64 + 16 * 64; idx += 512) {
        if (idx < 19 * 64) {
            int row = idx >> 6, d = idx & 63;
            float a = 0.f;
            #pragma unroll
            for (int k = 0; k < 32; k++) a = fmaf(sps[row][k], winw[d][k], a);
            sxpre[row][d] = a;
        } else {
            int i2 = idx - 19 * 64;
            int row = i2 >> 6, d = i2 & 63;
            float a = 0.f;
            #pragma unroll
            for (int k = 0; k < 32; k++) a = fmaf(sps[row + 3][k], winw[64 + d][k], a);
            g_gate[(base + row) * DI + d] = a;
        }
    }
    __syncthreads();

    for (int idx = tid; idx < 1024; idx += 512) {
        int r = idx >> 6, d = idx & 63;
        float acc = scb[d];
        #pragma unroll
        for (int kk = 0; kk < 4; kk++) acc = fmaf(sxpre[r + kk][d], scwT[kk][d], acc);
        float xv = acc / (1.f + __expf(-acc));
        sx[r][d] = xv;
        g_x[(base + r) * DI + d] = xv;
    }
    __syncthreads();

    for (int idx = tid; idx < 544; idx += 512) {
        int r = idx / 34, jj = idx % 34;
        float a = 0.f;
        #pragma unroll
        for (int dd = 0; dd < 64; dd++) a = fmaf(sx[r][dd], xpw[jj * 64 + dd], a);
        xd[r][jj] = a;
        if (jj >= 18)      g_Cm[(base + r) * DS + (jj - 18)] = a;
        else if (jj >= 2)  g_Bm[(base + r) * DS + (jj - 2)]  = a;
    }
    __syncthreads();

    for (int idx = tid; idx < 1024; idx += 512) {
        int r = idx >> 6, d = idx & 63;
        float dtraw = fmaf(xd[r][0], sdtw[d * 2],
                      fmaf(xd[r][1], sdtw[d * 2 + 1], sdtb[d]));
        float dtv = fmaxf(dtraw, 0.f) + log1pf(__expf(-fabsf(dtraw)));
        sdt[r][d] = dtv;
        g_dt[(base + r) * DI + d] = dtv;
    }
    __syncthreads();

    // sub-chunk scan summaries: 2 chains/thread, 2 sub-chunks of 8 t
    {
        int d = tid >> 3;
        int n0 = (tid & 7) * 2;
        float2 al = *(const float2*)(A_log + d * DS + n0);
        float a0 = -__expf(al.x), a1 = -__expf(al.y);
        int cA = l0 >> 3;                     // first sub-chunk idx in batch
        int chain = d * DS + n0;
        #pragma unroll
        for (int half = 0; half < 2; half++) {
            float ra0 = 1.f, ra1 = 1.f, rb0 = 0.f, rb1 = 0.f;
            #pragma unroll
            for (int tt = 0; tt < CT; tt++) {
                int t = half * CT + tt;
                float dtv = sdt[t][d];
                float dtx = dtv * sx[t][d];
                float B0 = xd[t][2 + n0], B1 = xd[t][3 + n0];
                float dA0 = __expf(dtv * a0), dA1 = __expf(dtv * a1);
                ra0 *= dA0; ra1 *= dA1;
                rb0 = fmaf(dA0, rb0, dtx * B0);
                rb1 = fmaf(dA1, rb1, dtx * B1);
            }
            size_t o = (size_t)(cA + half) * CHAINS + b * 1024 + chain;
            *(float2*)(g_ca + o) = make_float2(ra0, ra1);
            *(float2*)(g_cb + o) = make_float2(rb0, rb1);
        }
    }
}

// ---------------- K5: combine sub-chunk summaries -> entry states ----------
__global__ void __launch_bounds__(1024) k5_combine() {
    int chain = blockIdx.x * 1024 + threadIdx.x;
    float h = 0.f;
    #pragma unroll 8
    for (int c = 0; c < NCH; c++) {
        float a  = g_ca[c * CHAINS + chain];
        float bb = g_cb[c * CHAINS + chain];
        g_hi[c * CHAINS + chain] = h;
        h = fmaf(a, h, bb);
    }
}

// ---------------- K6: scan pass 2 (8 steps) + gate + out_proj ---------------
// grid = B_*NCH = 192, block 1024.
__global__ void __launch_bounds__(1024) k6_scan(const float* __restrict__ A_log,
                                                const float* __restrict__ Dp,
                                                const float* __restrict__ opw,
                                                float* __restrict__ out) {
    int b = blockIdx.x / NCH, c = blockIdx.x % NCH;
    int tid = threadIdx.x;
    int d = tid >> 4, n = tid & 15;
    __shared__ float sx[CT][DI], sg[CT][DI], sdt[CT][DI];
    __shared__ float sB[CT][DS], sC[CT][DS];
    __shared__ float ysm[CT][DI];
    __shared__ float sop[SOUT][DI + 1];
    int base = b * LSEQ + c * CT;
    if (tid < CT * DI) {
        int t = tid >> 6, dd = tid & 63;
        sx[t][dd]  = g_x[(base + t) * DI + dd];
        sg[t][dd]  = g_gate[(base + t) * DI + dd];
        sdt[t][dd] = g_dt[(base + t) * DI + dd];
    }
    if (tid < CT * DS) {
        int t = tid >> 4, nn = tid & 15;
        sB[t][nn] = g_Bm[(base + t) * DS + nn];
        sC[t][nn] = g_Cm[(base + t) * DS + nn];
    }
    { int idx = tid;          sop[idx >> 6][idx & 63] = opw[idx];
      idx = tid + 1024;       sop[idx >> 6][idx & 63] = opw[idx]; }
    float a = -__expf(A_log[tid]);
    float h = g_hi[c * CHAINS + b * 1024 + tid];
    float Dv = Dp[d];
    __syncthreads();
    #pragma unroll
    for (int t = 0; t < CT; t++) {
        float dtv = sdt[t][d];
        float dA  = __expf(dtv * a);
        float dbu = dtv * sB[t][n] * sx[t][d];
        h = fmaf(dA, h, dbu);
        float cb_ = h * sC[t][n];
        cb_ += __shfl_xor_sync(0xffffffffu, cb_, 8);
        cb_ += __shfl_xor_sync(0xffffffffu, cb_, 4);
        cb_ += __shfl_xor_sync(0xffffffffu, cb_, 2);
        cb_ += __shfl_xor_sync(0xffffffffu, cb_, 1);
        if (n == 0) {
            float y = cb_ + sx[t][d] * Dv;
            float g = sg[t][d];
            y *= g / (1.f + __expf(-g));
            ysm[t][d] = y;
        }
    }
    __syncthreads();
    if (tid < CT * SOUT) {                 // 256 threads: 8 t x 32 f
        int t = tid >> 5, f = tid & 31;
        float acc = 0.f;
        #pragma unroll
        for (int dd = 0; dd < DI; dd++) acc = fmaf(ysm[t][dd], sop[f][dd], acc);
        out[(size_t)(base + t) * SOUT + f] = acc;
    }
}

// ---------------- K7: z_prime = z*zw + zb + outer(sp, sp) ------------------
// grid = B_ x 96 sgroups x 6 t-strips = 1152 blocks; block (8,32); 128 t each.
#define STG_CS_V4(ptr, vx, vy, vz, vw) \
    asm volatile("st.global.cs.v4.f32 [%0], {%1,%2,%3,%4};" \
                 :: "l"(ptr), "f"(vx), "f"(vy), "f"(vz), "f"(vw) : "memory")

__global__ void __launch_bounds__(256) k7_z(const float* __restrict__ z,
                                            const float* __restrict__ zw,
                                            const float* __restrict__ zbv,
                                            const float* __restrict__ sp,
                                            float* __restrict__ outz) {
    int blk = blockIdx.x;
    int b = blk / 576;
    int rem = blk % 576;
    int s0 = (rem / 6) * 8;
    int tq = rem % 6;
    int tx = threadIdx.x;   // 0..7  (f/4)
    int ty = threadIdx.y;   // 0..31
    int tb = tq * 128 + ty * 4;
    float4 zw4 = ((const float4*)zw)[tx];
    float4 zb4 = ((const float4*)zbv)[tx];
    float4 sps[8];
    #pragma unroll
    for (int si = 0; si < 8; si++)
        sps[si] = ((const float4*)(sp + (size_t)(b * LSEQ + s0 + si) * SOUT))[tx];
    float4 spt[4];
    #pragma unroll
    for (int j = 0; j < 4; j++)
        spt[j] = ((const float4*)(sp + (size_t)(b * LSEQ + tb + j) * SOUT))[tx];
    const float* zrow = z + (size_t)(b * LSEQ) * LSEQ;
    float* orow = outz + (size_t)(b * LSEQ) * LSEQ * ZF;
    #pragma unroll
    for (int si = 0; si < 8; si++) {
        float4 zq = *(const float4*)(zrow + (size_t)(s0 + si) * LSEQ + tb);
        float zvals[4] = {zq.x, zq.y, zq.z, zq.w};
        #pragma unroll
        for (int j = 0; j < 4; j++) {
            float zv = zvals[j];
            float ox = fmaf(zv, zw4.x, zb4.x) + sps[si].x * spt[j].x;
            float oy = fmaf(zv, zw4.y, zb4.y) + sps[si].y * spt[j].y;
            float oz = fmaf(zv, zw4.z, zb4.z) + sps[si].z * spt[j].z;
            float ow = fmaf(zv, zw4.w, zb4.w) + sps[si].w * spt[j].w;
            float* p = orow + ((size_t)(s0 + si) * LSEQ + tb + j) * ZF + tx * 4;
            STG_CS_V4(p, ox, oy, oz, ow);
        }
    }
}

// ---------------- launch ----------------------------------------------------
extern "C" void kernel_launch(void* const* d_in, const int* in_sizes, int n_in,
                              void* d_out, int out_size) {
    const float* s        = (const float*)d_in[0];
    const float* z        = (const float*)d_in[1];
    const float* s_proj_w = (const float*)d_in[2];
    const float* s_proj_b = (const float*)d_in[3];
    const float* z_proj_w = (const float*)d_in[4];
    const float* z_proj_b = (const float*)d_in[5];
    const float* in_proj_w= (const float*)d_in[6];
    const float* conv_w   = (const float*)d_in[7];
    const float* conv_b   = (const float*)d_in[8];
    const float* x_proj_w = (const float*)d_in[9];
    const float* dt_proj_w= (const float*)d_in[10];
    const float* dt_proj_b= (const float*)d_in[11];
    const float* A_log    = (const float*)d_in[12];
    const float* Dp       = (const float*)d_in[13];
    const float* out_proj_w = (const float*)d_in[14];

    float* out    = (float*)d_out;
    float* sp_out = out;                       // [2,768,32]
    float* z_out  = out + (size_t)B_ * LSEQ * SOUT;

    ka_gemm<<<24 * KSP, 256>>>(s, s_proj_w);
    kb_fused<<<96, 512>>>(s_proj_b, in_proj_w, conv_w, conv_b,
                          x_proj_w, dt_proj_w, dt_proj_b, A_log);
    k5_combine<<<CHAINS / 1024, 1024>>>();
    k6_scan<<<B_ * NCH, 1024>>>(A_log, Dp, out_proj_w, sp_out);
    k7_z<<<1152, dim3(8, 32)>>>(z, z_proj_w, z_proj_b, sp_out, z_out);
}

// round 7
// speedup vs baseline: 2.5602x; 1.0004x over previous
#include <cuda_runtime.h>

#define B_   2
#define LSEQ 768
#define SIN  1280
#define SOUT 32
#define ZF   32
#define DI   64
#define DS   16
#define NCH  96     // sub-chunks along L
#define CT   8      // sub-chunk length
#define NROWS (B_*LSEQ)          // 1536
#define CHAINS (B_*DI*DS)        // 2048
#define KSP  8      // split-K for KA
#define KCA  (SIN/KSP)           // 160

// ---------------- scratch -----------------------------------------------
__device__ float g_part[KSP*NROWS*SOUT];   // KA partials (1.5 MB)
__device__ float g_x[NROWS*DI];            // conv+silu result
__device__ float g_gate[NROWS*DI];
__device__ float g_dt[NROWS*DI];
__device__ float g_Bm[NROWS*DS];
__device__ float g_Cm[NROWS*DS];
__device__ float g_ca[NCH*CHAINS];
__device__ float g_cb[NCH*CHAINS];
__device__ float g_hi[NCH*CHAINS];

// ---------------- KA: s' partials = s @ s_proj^T (split-K) ----------------
__global__ void __launch_bounds__(256) ka_gemm(const float* __restrict__ s,
                                               const float* __restrict__ spw) {
    __shared__ float sT[32][68];
    __shared__ float wdup[32][64];
    int tid = threadIdx.x;
    int rt = blockIdx.x >> 3;
    int ks = blockIdx.x & 7;
    int r0 = rt * 64;
    int kb = ks * KCA;
    int j  = tid & 31;
    int pg = tid >> 5;

    unsigned long long acc[4] = {0ull, 0ull, 0ull, 0ull};

    int lrow = tid >> 3;
    int lk4  = (tid & 7) * 4;
    int wj   = tid >> 3;
    int wk4  = (tid & 7) * 4;

    #pragma unroll 1
    for (int tile = 0; tile < KCA / 32; tile++) {
        int ktb = kb + tile * 32;
        __syncthreads();
        #pragma unroll
        for (int half = 0; half < 2; half++) {
            int row = lrow + half * 32;
            float4 v = *(const float4*)(s + (size_t)(r0 + row) * SIN + ktb + lk4);
            sT[lk4 + 0][row] = v.x; sT[lk4 + 1][row] = v.y;
            sT[lk4 + 2][row] = v.z; sT[lk4 + 3][row] = v.w;
        }
        {
            float4 w = *(const float4*)(spw + (size_t)wj * SIN + ktb + wk4);
            wdup[wk4 + 0][2 * wj] = w.x; wdup[wk4 + 0][2 * wj + 1] = w.x;
            wdup[wk4 + 1][2 * wj] = w.y; wdup[wk4 + 1][2 * wj + 1] = w.y;
            wdup[wk4 + 2][2 * wj] = w.z; wdup[wk4 + 2][2 * wj + 1] = w.z;
            wdup[wk4 + 3][2 * wj] = w.w; wdup[wk4 + 3][2 * wj + 1] = w.w;
        }
        __syncthreads();
        #pragma unroll
        for (int k = 0; k < 32; k++) {
            ulonglong2 pA = *(const ulonglong2*)&sT[k][pg * 8];
            ulonglong2 pB = *(const ulonglong2*)&sT[k][pg * 8 + 4];
            unsigned long long wv = *(const unsigned long long*)&wdup[k][2 * j];
            asm("fma.rn.f32x2 %0, %1, %2, %0;" : "+l"(acc[0]) : "l"(pA.x), "l"(wv));
            asm("fma.rn.f32x2 %0, %1, %2, %0;" : "+l"(acc[1]) : "l"(pA.y), "l"(wv));
            asm("fma.rn.f32x2 %0, %1, %2, %0;" : "+l"(acc[2]) : "l"(pB.x), "l"(wv));
            asm("fma.rn.f32x2 %0, %1, %2, %0;" : "+l"(acc[3]) : "l"(pB.y), "l"(wv));
        }
    }
    #pragma unroll
    for (int q = 0; q < 4; q++) {
        float2 v = *(float2*)&acc[q];
        int row = r0 + pg * 8 + q * 2;
        g_part[(size_t)ks * NROWS * SOUT + (size_t)row * SOUT + j]       = v.x;
        g_part[(size_t)ks * NROWS * SOUT + (size_t)(row + 1) * SOUT + j] = v.y;
    }
}

// ---------------- KB: fused reduce + in_proj + conv + x_proj + dt + chunk --
__global__ void __launch_bounds__(512) kb_fused(const float* __restrict__ spb,
                                                const float* __restrict__ inw,
                                                const float* __restrict__ convw,
                                                const float* __restrict__ convb,
                                                const float* __restrict__ xpw,
                                                const float* __restrict__ dtw,
                                                const float* __restrict__ dtb,
                                                const float* __restrict__ A_log) {
    __shared__ float sps[19][33];
    __shared__ float winw[128][33];
    __shared__ float sxpre[19][64];
    __shared__ float sx[16][64];
    __shared__ float xd[16][34];
    __shared__ float sdt[16][64];
    __shared__ float scwT[4][64];
    __shared__ float scb[64], sdtw[128], sdtb[64];

    int tid = threadIdx.x;
    int base = blockIdx.x * 16;
    int b = base / LSEQ;
    int l0 = base % LSEQ;

    for (int idx = tid; idx < 19 * SOUT; idx += 512) {
        int row = idx >> 5, jj = idx & 31;
        int grow = base + row - 3;
        float v = 0.f;
        if (l0 != 0 || row >= 3) {
            v = spb[jj];
            #pragma unroll
            for (int ks = 0; ks < KSP; ks++)
                v += g_part[(size_t)ks * NROWS * SOUT + (size_t)grow * SOUT + jj];
        }
        sps[row][jj] = v;
    }
    for (int idx = tid; idx < 128 * 32; idx += 512)
        winw[idx >> 5][idx & 31] = inw[idx];
    if (tid < 256)        scwT[tid & 3][tid >> 2] = convw[tid];
    else if (tid < 320)   scb[tid - 256] = convb[tid - 256];
    else if (tid < 448)   sdtw[tid - 320] = dtw[tid - 320];
    else                  sdtb[tid - 448] = dtb[tid - 448];
    __syncthreads();

    for (int idx = tid; idx < 19 * 64 + 16 * 64; idx += 512) {
        if (idx < 19 * 64) {
            int row = idx >> 6, d = idx & 63;
            float a = 0.f;
            #pragma unroll
            for (int k = 0; k < 32; k++) a = fmaf(sps[row][k], winw[d][k], a);
            sxpre[row][d] = a;
        } else {
            int i2 = idx - 19 * 64;
            int row = i2 >> 6, d = i2 & 63;
            float a = 0.f;
            #pragma unroll
            for (int k = 0; k < 32; k++) a = fmaf(sps[row + 3][k], winw[64 + d][k], a);
            g_gate[(base + row) * DI + d] = a;
        }
    }
    __syncthreads();

    for (int idx = tid; idx < 1024; idx += 512) {
        int r = idx >> 6, d = idx & 63;
        float acc = scb[d];
        #pragma unroll
        for (int kk = 0; kk < 4; kk++) acc = fmaf(sxpre[r + kk][d], scwT[kk][d], acc);
        float xv = acc / (1.f + __expf(-acc));
        sx[r][d] = xv;
        g_x[(base + r) * DI + d] = xv;
    }
    __syncthreads();

    for (int idx = tid; idx < 544; idx += 512) {
        int r = idx / 34, jj = idx % 34;
        float a = 0.f;
        #pragma unroll
        for (int dd = 0; dd < 64; dd++) a = fmaf(sx[r][dd], xpw[jj * 64 + dd], a);
        xd[r][jj] = a;
        if (jj >= 18)      g_Cm[(base + r) * DS + (jj - 18)] = a;
        else if (jj >= 2)  g_Bm[(base + r) * DS + (jj - 2)]  = a;
    }
    __syncthreads();

    for (int idx = tid; idx < 1024; idx += 512) {
        int r = idx >> 6, d = idx & 63;
        float dtraw = fmaf(xd[r][0], sdtw[d * 2],
                      fmaf(xd[r][1], sdtw[d * 2 + 1], sdtb[d]));
        float dtv = fmaxf(dtraw, 0.f) + log1pf(__expf(-fabsf(dtraw)));
        sdt[r][d] = dtv;
        g_dt[(base + r) * DI + d] = dtv;
    }
    __syncthreads();

    {
        int d = tid >> 3;
        int n0 = (tid & 7) * 2;
        float2 al = *(const float2*)(A_log + d * DS + n0);
        float a0 = -__expf(al.x), a1 = -__expf(al.y);
        int cA = l0 >> 3;
        int chain = d * DS + n0;
        #pragma unroll
        for (int half = 0; half < 2; half++) {
            float ra0 = 1.f, ra1 = 1.f, rb0 = 0.f, rb1 = 0.f;
            #pragma unroll
            for (int tt = 0; tt < CT; tt++) {
                int t = half * CT + tt;
                float dtv = sdt[t][d];
                float dtx = dtv * sx[t][d];
                float B0 = xd[t][2 + n0], B1 = xd[t][3 + n0];
                float dA0 = __expf(dtv * a0), dA1 = __expf(dtv * a1);
                ra0 *= dA0; ra1 *= dA1;
                rb0 = fmaf(dA0, rb0, dtx * B0);
                rb1 = fmaf(dA1, rb1, dtx * B1);
            }
            size_t o = (size_t)(cA + half) * CHAINS + b * 1024 + chain;
            *(float2*)(g_ca + o) = make_float2(ra0, ra1);
            *(float2*)(g_cb + o) = make_float2(rb0, rb1);
        }
    }
}

// ---------------- K5: combine sub-chunk summaries -> entry states ----------
__global__ void __launch_bounds__(1024) k5_combine() {
    int chain = blockIdx.x * 1024 + threadIdx.x;
    float h = 0.f;
    #pragma unroll 8
    for (int c = 0; c < NCH; c++) {
        float a  = g_ca[c * CHAINS + chain];
        float bb = g_cb[c * CHAINS + chain];
        g_hi[c * CHAINS + chain] = h;
        h = fmaf(a, h, bb);
    }
}

// ---------------- K6: scan pass 2, 4 n per thread, 256-thread blocks --------
// grid = B_*NCH = 192 blocks.
__global__ void __launch_bounds__(256) k6_scan(const float* __restrict__ A_log,
                                               const float* __restrict__ Dp,
                                               const float* __restrict__ opw,
                                               float* __restrict__ out) {
    int b = blockIdx.x / NCH, c = blockIdx.x % NCH;
    int tid = threadIdx.x;
    int d  = tid >> 2;
    int ng = (tid & 3) * 4;
    __shared__ float sx[CT][DI], sg[CT][DI], sdt[CT][DI];
    __shared__ float sB[CT][DS], sC[CT][DS];
    __shared__ float ysm[CT][DI];
    __shared__ float sop[SOUT][DI + 1];
    int base = b * LSEQ + c * CT;

    // stage tiles: 512 elems each -> 2 per thread
    #pragma unroll
    for (int e = 0; e < 2; e++) {
        int idx = tid + e * 256;
        int t = idx >> 6, dd = idx & 63;
        sx[t][dd]  = g_x[(base + t) * DI + dd];
        sg[t][dd]  = g_gate[(base + t) * DI + dd];
        sdt[t][dd] = g_dt[(base + t) * DI + dd];
    }
    if (tid < CT * DS) {
        int t = tid >> 4, nn = tid & 15;
        sB[t][nn] = g_Bm[(base + t) * DS + nn];
        sC[t][nn] = g_Cm[(base + t) * DS + nn];
    }
    #pragma unroll
    for (int e = 0; e < 8; e++) {
        int idx = tid + e * 256;
        sop[idx >> 6][idx & 63] = opw[idx];
    }
    float4 av = *(const float4*)(A_log + d * DS + ng);
    float a0 = -__expf(av.x), a1 = -__expf(av.y);
    float a2 = -__expf(av.z), a3 = -__expf(av.w);
    float4 hv = *(const float4*)(g_hi + (size_t)c * CHAINS + b * 1024 + d * DS + ng);
    float h0 = hv.x, h1 = hv.y, h2 = hv.z, h3 = hv.w;
    float Dv = Dp[d];
    __syncthreads();

    #pragma unroll
    for (int t = 0; t < CT; t++) {
        float dtv = sdt[t][d];
        float xv  = sx[t][d];
        float dtx = dtv * xv;
        float dA0 = __expf(dtv * a0), dA1 = __expf(dtv * a1);
        float dA2 = __expf(dtv * a2), dA3 = __expf(dtv * a3);
        h0 = fmaf(dA0, h0, dtx * sB[t][ng + 0]);
        h1 = fmaf(dA1, h1, dtx * sB[t][ng + 1]);
        h2 = fmaf(dA2, h2, dtx * sB[t][ng + 2]);
        h3 = fmaf(dA3, h3, dtx * sB[t][ng + 3]);
        float yp = h0 * sC[t][ng + 0] + h1 * sC[t][ng + 1]
                 + h2 * sC[t][ng + 2] + h3 * sC[t][ng + 3];
        yp += __shfl_xor_sync(0xffffffffu, yp, 1);
        yp += __shfl_xor_sync(0xffffffffu, yp, 2);
        if ((tid & 3) == 0) {
            float y = yp + xv * Dv;
            float g = sg[t][d];
            y *= g / (1.f + __expf(-g));
            ysm[t][d] = y;
        }
    }
    __syncthreads();
    {   // out_proj: 256 threads = 8 t x 32 f
        int t = tid >> 5, f = tid & 31;
        float acc = 0.f;
        #pragma unroll
        for (int dd = 0; dd < DI; dd++) acc = fmaf(ysm[t][dd], sop[f][dd], acc);
        out[(size_t)(base + t) * SOUT + f] = acc;
    }
}

// ---------------- K7: z_prime = z*zw + zb + outer(sp, sp) ------------------
// grid = 1152 blocks; block (8,32). Loads batched ahead of streaming stores.
__global__ void __launch_bounds__(256) k7_z(const float* __restrict__ z,
                                            const float* __restrict__ zw,
                                            const float* __restrict__ zbv,
                                            const float* __restrict__ sp,
                                            float* __restrict__ outz) {
    int blk = blockIdx.x;
    int b = blk / 576;
    int rem = blk % 576;
    int s0 = (rem / 6) * 8;
    int tq = rem % 6;
    int tx = threadIdx.x;   // 0..7  (f/4)
    int ty = threadIdx.y;   // 0..31
    int tb = tq * 128 + ty * 4;
    const float* zrow = z + (size_t)(b * LSEQ) * LSEQ;
    float* orow = outz + (size_t)(b * LSEQ) * LSEQ * ZF;

    // batch ALL global loads first (MLP)
    float4 zq[8];
    #pragma unroll
    for (int si = 0; si < 8; si++)
        zq[si] = *(const float4*)(zrow + (size_t)(s0 + si) * LSEQ + tb);
    float4 sps[8];
    #pragma unroll
    for (int si = 0; si < 8; si++)
        sps[si] = ((const float4*)(sp + (size_t)(b * LSEQ + s0 + si) * SOUT))[tx];
    float4 spt[4];
    #pragma unroll
    for (int j = 0; j < 4; j++)
        spt[j] = ((const float4*)(sp + (size_t)(b * LSEQ + tb + j) * SOUT))[tx];
    float4 zw4 = ((const float4*)zw)[tx];
    float4 zb4 = ((const float4*)zbv)[tx];

    #pragma unroll
    for (int si = 0; si < 8; si++) {
        float zvals[4] = {zq[si].x, zq[si].y, zq[si].z, zq[si].w};
        #pragma unroll
        for (int j = 0; j < 4; j++) {
            float zv = zvals[j];
            float4 o;
            o.x = fmaf(zv, zw4.x, zb4.x) + sps[si].x * spt[j].x;
            o.y = fmaf(zv, zw4.y, zb4.y) + sps[si].y * spt[j].y;
            o.z = fmaf(zv, zw4.z, zb4.z) + sps[si].z * spt[j].z;
            o.w = fmaf(zv, zw4.w, zb4.w) + sps[si].w * spt[j].w;
            __stcs((float4*)(orow + ((size_t)(s0 + si) * LSEQ + tb + j) * ZF + tx * 4), o);
        }
    }
}

// ---------------- launch ----------------------------------------------------
extern "C" void kernel_launch(void* const* d_in, const int* in_sizes, int n_in,
                              void* d_out, int out_size) {
    const float* s        = (const float*)d_in[0];
    const float* z        = (const float*)d_in[1];
    const float* s_proj_w = (const float*)d_in[2];
    const float* s_proj_b = (const float*)d_in[3];
    const float* z_proj_w = (const float*)d_in[4];
    const float* z_proj_b = (const float*)d_in[5];
    const float* in_proj_w= (const float*)d_in[6];
    const float* conv_w   = (const float*)d_in[7];
    const float* conv_b   = (const float*)d_in[8];
    const float* x_proj_w = (const float*)d_in[9];
    const float* dt_proj_w= (const float*)d_in[10];
    const float* dt_proj_b= (const float*)d_in[11];
    const float* A_log    = (const float*)d_in[12];
    const float* Dp       = (const float*)d_in[13];
    const float* out_proj_w = (const float*)d_in[14];

    float* out    = (float*)d_out;
    float* sp_out = out;                       // [2,768,32]
    float* z_out  = out + (size_t)B_ * LSEQ * SOUT;

    ka_gemm<<<24 * KSP, 256>>>(s, s_proj_w);
    kb_fused<<<96, 512>>>(s_proj_b, in_proj_w, conv_w, conv_b,
                          x_proj_w, dt_proj_w, dt_proj_b, A_log);
    k5_combine<<<CHAINS / 1024, 1024>>>();
    k6_scan<<<B_ * NCH, 256>>>(A_log, Dp, out_proj_w, sp_out);
    k7_z<<<1152, dim3(8, 32)>>>(z, z_proj_w, z_proj_b, sp_out, z_out);
}

// round 8
// speedup vs baseline: 2.7258x; 1.0647x over previous
#include <cuda_runtime.h>

#define B_   2
#define LSEQ 768
#define SIN  1280
#define SOUT 32
#define ZF   32
#define DI   64
#define DS   16
#define NCH  96     // sub-chunks along L
#define CT   8      // sub-chunk length
#define NROWS (B_*LSEQ)          // 1536
#define CHAINS (B_*DI*DS)        // 2048
#define KSP  8      // split-K for KA
#define KCA  (SIN/KSP)           // 160

// ---------------- scratch -----------------------------------------------
__device__ float g_part[KSP*NROWS*SOUT];   // KA partials (1.5 MB)
__device__ float g_x[NROWS*DI];            // conv+silu result
__device__ float g_gate[NROWS*DI];
__device__ float g_dt[NROWS*DI];
__device__ float g_Bm[NROWS*DS];
__device__ float g_Cm[NROWS*DS];
__device__ float g_ca[NCH*CHAINS];
__device__ float g_cb[NCH*CHAINS];

// ---------------- KA: s' partials = s @ s_proj^T (split-K) ----------------
__global__ void __launch_bounds__(256) ka_gemm(const float* __restrict__ s,
                                               const float* __restrict__ spw) {
    __shared__ float sT[32][68];
    __shared__ float wdup[32][64];
    int tid = threadIdx.x;
    int rt = blockIdx.x >> 3;
    int ks = blockIdx.x & 7;
    int r0 = rt * 64;
    int kb = ks * KCA;
    int j  = tid & 31;
    int pg = tid >> 5;

    unsigned long long acc[4] = {0ull, 0ull, 0ull, 0ull};

    int lrow = tid >> 3;
    int lk4  = (tid & 7) * 4;
    int wj   = tid >> 3;
    int wk4  = (tid & 7) * 4;

    #pragma unroll 1
    for (int tile = 0; tile < KCA / 32; tile++) {
        int ktb = kb + tile * 32;
        __syncthreads();
        #pragma unroll
        for (int half = 0; half < 2; half++) {
            int row = lrow + half * 32;
            float4 v = *(const float4*)(s + (size_t)(r0 + row) * SIN + ktb + lk4);
            sT[lk4 + 0][row] = v.x; sT[lk4 + 1][row] = v.y;
            sT[lk4 + 2][row] = v.z; sT[lk4 + 3][row] = v.w;
        }
        {
            float4 w = *(const float4*)(spw + (size_t)wj * SIN + ktb + wk4);
            wdup[wk4 + 0][2 * wj] = w.x; wdup[wk4 + 0][2 * wj + 1] = w.x;
            wdup[wk4 + 1][2 * wj] = w.y; wdup[wk4 + 1][2 * wj + 1] = w.y;
            wdup[wk4 + 2][2 * wj] = w.z; wdup[wk4 + 2][2 * wj + 1] = w.z;
            wdup[wk4 + 3][2 * wj] = w.w; wdup[wk4 + 3][2 * wj + 1] = w.w;
        }
        __syncthreads();
        #pragma unroll
        for (int k = 0; k < 32; k++) {
            ulonglong2 pA = *(const ulonglong2*)&sT[k][pg * 8];
            ulonglong2 pB = *(const ulonglong2*)&sT[k][pg * 8 + 4];
            unsigned long long wv = *(const unsigned long long*)&wdup[k][2 * j];
            asm("fma.rn.f32x2 %0, %1, %2, %0;" : "+l"(acc[0]) : "l"(pA.x), "l"(wv));
            asm("fma.rn.f32x2 %0, %1, %2, %0;" : "+l"(acc[1]) : "l"(pA.y), "l"(wv));
            asm("fma.rn.f32x2 %0, %1, %2, %0;" : "+l"(acc[2]) : "l"(pB.x), "l"(wv));
            asm("fma.rn.f32x2 %0, %1, %2, %0;" : "+l"(acc[3]) : "l"(pB.y), "l"(wv));
        }
    }
    #pragma unroll
    for (int q = 0; q < 4; q++) {
        float2 v = *(float2*)&acc[q];
        int row = r0 + pg * 8 + q * 2;
        g_part[(size_t)ks * NROWS * SOUT + (size_t)row * SOUT + j]       = v.x;
        g_part[(size_t)ks * NROWS * SOUT + (size_t)(row + 1) * SOUT + j] = v.y;
    }
}

// ---------------- KB: fused reduce + in_proj + conv + x_proj + dt + chunk --
__global__ void __launch_bounds__(512) kb_fused(const float* __restrict__ spb,
                                                const float* __restrict__ inw,
                                                const float* __restrict__ convw,
                                                const float* __restrict__ convb,
                                                const float* __restrict__ xpw,
                                                const float* __restrict__ dtw,
                                                const float* __restrict__ dtb,
                                                const float* __restrict__ A_log) {
    __shared__ float sps[19][33];
    __shared__ float winw[128][33];
    __shared__ float sxpre[19][64];
    __shared__ float sx[16][64];
    __shared__ float xd[16][34];
    __shared__ float sdt[16][64];
    __shared__ float scwT[4][64];
    __shared__ float scb[64], sdtw[128], sdtb[64];

    int tid = threadIdx.x;
    int base = blockIdx.x * 16;
    int b = base / LSEQ;
    int l0 = base % LSEQ;

    for (int idx = tid; idx < 19 * SOUT; idx += 512) {
        int row = idx >> 5, jj = idx & 31;
        int grow = base + row - 3;
        float v = 0.f;
        if (l0 != 0 || row >= 3) {
            v = spb[jj];
            #pragma unroll
            for (int ks = 0; ks < KSP; ks++)
                v += g_part[(size_t)ks * NROWS * SOUT + (size_t)grow * SOUT + jj];
        }
        sps[row][jj] = v;
    }
    for (int idx = tid; idx < 128 * 32; idx += 512)
        winw[idx >> 5][idx & 31] = inw[idx];
    if (tid < 256)        scwT[tid & 3][tid >> 2] = convw[tid];
    else if (tid < 320)   scb[tid - 256] = convb[tid - 256];
    else if (tid < 448)   sdtw[tid - 320] = dtw[tid - 320];
    else                  sdtb[tid - 448] = dtb[tid - 448];
    __syncthreads();

    for (int idx = tid; idx < 19 * 64 + 16 * 64; idx += 512) {
        if (idx < 19 * 64) {
            int row = idx >> 6, d = idx & 63;
            float a = 0.f;
            #pragma unroll
            for (int k = 0; k < 32; k++) a = fmaf(sps[row][k], winw[d][k], a);
            sxpre[row][d] = a;
        } else {
            int i2 = idx - 19 * 64;
            int row = i2 >> 6, d = i2 & 63;
            float a = 0.f;
            #pragma unroll
            for (int k = 0; k < 32; k++) a = fmaf(sps[row + 3][k], winw[64 + d][k], a);
            g_gate[(base + row) * DI + d] = a;
        }
    }
    __syncthreads();

    for (int idx = tid; idx < 1024; idx += 512) {
        int r = idx >> 6, d = idx & 63;
        float acc = scb[d];
        #pragma unroll
        for (int kk = 0; kk < 4; kk++) acc = fmaf(sxpre[r + kk][d], scwT[kk][d], acc);
        float xv = acc / (1.f + __expf(-acc));
        sx[r][d] = xv;
        g_x[(base + r) * DI + d] = xv;
    }
    __syncthreads();

    for (int idx = tid; idx < 544; idx += 512) {
        int r = idx / 34, jj = idx % 34;
        float a = 0.f;
        #pragma unroll
        for (int dd = 0; dd < 64; dd++) a = fmaf(sx[r][dd], xpw[jj * 64 + dd], a);
        xd[r][jj] = a;
        if (jj >= 18)      g_Cm[(base + r) * DS + (jj - 18)] = a;
        else if (jj >= 2)  g_Bm[(base + r) * DS + (jj - 2)]  = a;
    }
    __syncthreads();

    for (int idx = tid; idx < 1024; idx += 512) {
        int r = idx >> 6, d = idx & 63;
        float dtraw = fmaf(xd[r][0], sdtw[d * 2],
                      fmaf(xd[r][1], sdtw[d * 2 + 1], sdtb[d]));
        float dtv = fmaxf(dtraw, 0.f) + log1pf(__expf(-fabsf(dtraw)));
        sdt[r][d] = dtv;
        g_dt[(base + r) * DI + d] = dtv;
    }
    __syncthreads();

    {
        int d = tid >> 3;
        int n0 = (tid & 7) * 2;
        float2 al = *(const float2*)(A_log + d * DS + n0);
        float a0 = -__expf(al.x), a1 = -__expf(al.y);
        int cA = l0 >> 3;
        #pragma unroll
        for (int half = 0; half < 2; half++) {
            float ra0 = 1.f, ra1 = 1.f, rb0 = 0.f, rb1 = 0.f;
            #pragma unroll
            for (int tt = 0; tt < CT; tt++) {
                int t = half * CT + tt;
                float dtv = sdt[t][d];
                float dtx = dtv * sx[t][d];
                float B0 = xd[t][2 + n0], B1 = xd[t][3 + n0];
                float dA0 = __expf(dtv * a0), dA1 = __expf(dtv * a1);
                ra0 *= dA0; ra1 *= dA1;
                rb0 = fmaf(dA0, rb0, dtx * B0);
                rb1 = fmaf(dA1, rb1, dtx * B1);
            }
            size_t o = (size_t)(cA + half) * CHAINS + b * 1024 + 2 * tid;
            *(float2*)(g_ca + o) = make_float2(ra0, ra1);
            *(float2*)(g_cb + o) = make_float2(rb0, rb1);
        }
    }
}

// ---------------- K6: fused prefix-combine + scan + gate + out_proj --------
// grid = B_*NCH = 192 blocks, 512 threads, 2 chains per thread (chain = 2*tid).
__global__ void __launch_bounds__(512) k6_scan(const float* __restrict__ A_log,
                                               const float* __restrict__ Dp,
                                               const float* __restrict__ opw,
                                               float* __restrict__ out) {
    int b = blockIdx.x / NCH, c = blockIdx.x % NCH;
    int tid = threadIdx.x;
    int d  = tid >> 3;
    int n0 = (tid & 7) * 2;
    __shared__ float sx[CT][DI], sg[CT][DI], sdt[CT][DI];
    __shared__ float sB[CT][DS], sC[CT][DS];
    __shared__ float ysm[CT][DI];
    __shared__ float sop[SOUT][DI + 1];
    int base = b * LSEQ + c * CT;

    {   // stage tiles (512 elems each -> 1/thread)
        int t = tid >> 6, dd = tid & 63;
        sx[t][dd]  = g_x[(base + t) * DI + dd];
        sg[t][dd]  = g_gate[(base + t) * DI + dd];
        sdt[t][dd] = g_dt[(base + t) * DI + dd];
    }
    if (tid < CT * DS) {
        int t = tid >> 4, nn = tid & 15;
        sB[t][nn] = g_Bm[(base + t) * DS + nn];
    } else if (tid < 2 * CT * DS) {
        int i = tid - CT * DS;
        int t = i >> 4, nn = i & 15;
        sC[t][nn] = g_Cm[(base + t) * DS + nn];
    }
    #pragma unroll
    for (int e = 0; e < 4; e++) {
        int idx = tid + e * 512;
        sop[idx >> 6][idx & 63] = opw[idx];
    }

    // prefix combine over sub-chunks 0..c-1 for this thread's 2 chains
    float h0 = 0.f, h1 = 0.f;
    {
        size_t gc = (size_t)b * 1024 + 2 * tid;
        #pragma unroll 4
        for (int cc = 0; cc < c; cc++) {
            float2 av = *(const float2*)(g_ca + (size_t)cc * CHAINS + gc);
            float2 bv = *(const float2*)(g_cb + (size_t)cc * CHAINS + gc);
            h0 = fmaf(av.x, h0, bv.x);
            h1 = fmaf(av.y, h1, bv.y);
        }
    }
    float2 alv = *(const float2*)(A_log + 2 * tid);
    float a0 = -__expf(alv.x), a1 = -__expf(alv.y);
    float Dv = Dp[d];
    __syncthreads();

    #pragma unroll
    for (int t = 0; t < CT; t++) {
        float dtv = sdt[t][d];
        float xv  = sx[t][d];
        float dtx = dtv * xv;
        float dA0 = __expf(dtv * a0), dA1 = __expf(dtv * a1);
        h0 = fmaf(dA0, h0, dtx * sB[t][n0 + 0]);
        h1 = fmaf(dA1, h1, dtx * sB[t][n0 + 1]);
        float yp = h0 * sC[t][n0 + 0] + h1 * sC[t][n0 + 1];
        yp += __shfl_xor_sync(0xffffffffu, yp, 1);
        yp += __shfl_xor_sync(0xffffffffu, yp, 2);
        yp += __shfl_xor_sync(0xffffffffu, yp, 4);
        if ((tid & 7) == 0) {
            float y = yp + xv * Dv;
            float g = sg[t][d];
            y *= g / (1.f + __expf(-g));
            ysm[t][d] = y;
        }
    }
    __syncthreads();
    if (tid < CT * SOUT) {                 // 256 threads: 8 t x 32 f
        int t = tid >> 5, f = tid & 31;
        float acc = 0.f;
        #pragma unroll
        for (int dd = 0; dd < DI; dd++) acc = fmaf(ysm[t][dd], sop[f][dd], acc);
        out[(size_t)(base + t) * SOUT + f] = acc;
    }
}

// ---------------- K7: z_prime = z*zw + zb + outer(sp, sp) ------------------
// grid = B_ x 96 s-groups x 8 t-strips = 1536 blocks; block 256.
// Per block: 8 s-rows x 96 contiguous t. Warp stores are 512B contiguous.
__global__ void __launch_bounds__(256) k7_z(const float* __restrict__ z,
                                            const float* __restrict__ zw,
                                            const float* __restrict__ zbv,
                                            const float* __restrict__ sp,
                                            float* __restrict__ outz) {
    int blk = blockIdx.x;
    int b = blk / 768;
    int rem = blk % 768;
    int s0 = (rem >> 3) * 8;
    int t0 = (rem & 7) * 96;
    int tx = threadIdx.x & 7;       // f-quad
    int tl = threadIdx.x >> 3;      // 0..31 (t lane)
    const float* zrow = z + (size_t)(b * LSEQ) * LSEQ;
    float* orow = outz + (size_t)(b * LSEQ) * LSEQ * ZF;

    float4 zw4 = ((const float4*)zw)[tx];
    float4 zb4 = ((const float4*)zbv)[tx];
    float4 sps[8];
    #pragma unroll
    for (int si = 0; si < 8; si++)
        sps[si] = ((const float4*)(sp + (size_t)(b * LSEQ + s0 + si) * SOUT))[tx];

    #pragma unroll
    for (int pass = 0; pass < 3; pass++) {
        int t = t0 + pass * 32 + tl;
        float4 spt = ((const float4*)(sp + (size_t)(b * LSEQ + t) * SOUT))[tx];
        float zv[8];
        #pragma unroll
        for (int si = 0; si < 8; si++)
            zv[si] = zrow[(size_t)(s0 + si) * LSEQ + t];
        #pragma unroll
        for (int si = 0; si < 8; si++) {
            float4 o;
            o.x = fmaf(zv[si], zw4.x, zb4.x) + sps[si].x * spt.x;
            o.y = fmaf(zv[si], zw4.y, zb4.y) + sps[si].y * spt.y;
            o.z = fmaf(zv[si], zw4.z, zb4.z) + sps[si].z * spt.z;
            o.w = fmaf(zv[si], zw4.w, zb4.w) + sps[si].w * spt.w;
            __stcs((float4*)(orow + ((size_t)(s0 + si) * LSEQ + t) * ZF + tx * 4), o);
        }
    }
}

// ---------------- launch ----------------------------------------------------
extern "C" void kernel_launch(void* const* d_in, const int* in_sizes, int n_in,
                              void* d_out, int out_size) {
    const float* s        = (const float*)d_in[0];
    const float* z        = (const float*)d_in[1];
    const float* s_proj_w = (const float*)d_in[2];
    const float* s_proj_b = (const float*)d_in[3];
    const float* z_proj_w = (const float*)d_in[4];
    const float* z_proj_b = (const float*)d_in[5];
    const float* in_proj_w= (const float*)d_in[6];
    const float* conv_w   = (const float*)d_in[7];
    const float* conv_b   = (const float*)d_in[8];
    const float* x_proj_w = (const float*)d_in[9];
    const float* dt_proj_w= (const float*)d_in[10];
    const float* dt_proj_b= (const float*)d_in[11];
    const float* A_log    = (const float*)d_in[12];
    const float* Dp       = (const float*)d_in[13];
    const float* out_proj_w = (const float*)d_in[14];

    float* out    = (float*)d_out;
    float* sp_out = out;                       // [2,768,32]
    float* z_out  = out + (size_t)B_ * LSEQ * SOUT;

    ka_gemm<<<24 * KSP, 256>>>(s, s_proj_w);
    kb_fused<<<96, 512>>>(s_proj_b, in_proj_w, conv_w, conv_b,
                          x_proj_w, dt_proj_w, dt_proj_b, A_log);
    k6_scan<<<B_ * NCH, 512>>>(A_log, Dp, out_proj_w, sp_out);
    k7_z<<<1536, 256>>>(z, z_proj_w, z_proj_b, sp_out, z_out);
}

// round 9
// speedup vs baseline: 2.8301x; 1.0383x over previous
#include <cuda_runtime.h>

#define B_   2
#define LSEQ 768
#define SIN  1280
#define SOUT 32
#define ZF   32
#define DI   64
#define DS   16
#define NCH  96     // sub-chunks along L
#define CT   8      // sub-chunk length
#define NROWS (B_*LSEQ)          // 1536
#define CHAINS (B_*DI*DS)        // 2048
#define KSP  8      // split-K for KA
#define KCA  (SIN/KSP)           // 160

// ---------------- scratch -----------------------------------------------
__device__ float g_part[KSP*NROWS*SOUT];   // KA partials (1.5 MB)
__device__ float g_x[NROWS*DI];            // conv+silu result
__device__ float g_gate[NROWS*DI];
__device__ float g_dt[NROWS*DI];
__device__ float g_Bm[NROWS*DS];
__device__ float g_Cm[NROWS*DS];
__device__ float g_ca[NCH*CHAINS];
__device__ float g_cb[NCH*CHAINS];

// ---------------- KA: s' partials = s @ s_proj^T (split-K) ----------------
__global__ void __launch_bounds__(256) ka_gemm(const float* __restrict__ s,
                                               const float* __restrict__ spw) {
    __shared__ float sT[32][68];
    __shared__ float wdup[32][64];
    int tid = threadIdx.x;
    int rt = blockIdx.x >> 3;
    int ks = blockIdx.x & 7;
    int r0 = rt * 64;
    int kb = ks * KCA;
    int j  = tid & 31;
    int pg = tid >> 5;

    unsigned long long acc[4] = {0ull, 0ull, 0ull, 0ull};

    int lrow = tid >> 3;
    int lk4  = (tid & 7) * 4;
    int wj   = tid >> 3;
    int wk4  = (tid & 7) * 4;

    #pragma unroll 1
    for (int tile = 0; tile < KCA / 32; tile++) {
        int ktb = kb + tile * 32;
        __syncthreads();
        #pragma unroll
        for (int half = 0; half < 2; half++) {
            int row = lrow + half * 32;
            float4 v = *(const float4*)(s + (size_t)(r0 + row) * SIN + ktb + lk4);
            sT[lk4 + 0][row] = v.x; sT[lk4 + 1][row] = v.y;
            sT[lk4 + 2][row] = v.z; sT[lk4 + 3][row] = v.w;
        }
        {
            float4 w = *(const float4*)(spw + (size_t)wj * SIN + ktb + wk4);
            wdup[wk4 + 0][2 * wj] = w.x; wdup[wk4 + 0][2 * wj + 1] = w.x;
            wdup[wk4 + 1][2 * wj] = w.y; wdup[wk4 + 1][2 * wj + 1] = w.y;
            wdup[wk4 + 2][2 * wj] = w.z; wdup[wk4 + 2][2 * wj + 1] = w.z;
            wdup[wk4 + 3][2 * wj] = w.w; wdup[wk4 + 3][2 * wj + 1] = w.w;
        }
        __syncthreads();
        #pragma unroll
        for (int k = 0; k < 32; k++) {
            ulonglong2 pA = *(const ulonglong2*)&sT[k][pg * 8];
            ulonglong2 pB = *(const ulonglong2*)&sT[k][pg * 8 + 4];
            unsigned long long wv = *(const unsigned long long*)&wdup[k][2 * j];
            asm("fma.rn.f32x2 %0, %1, %2, %0;" : "+l"(acc[0]) : "l"(pA.x), "l"(wv));
            asm("fma.rn.f32x2 %0, %1, %2, %0;" : "+l"(acc[1]) : "l"(pA.y), "l"(wv));
            asm("fma.rn.f32x2 %0, %1, %2, %0;" : "+l"(acc[2]) : "l"(pB.x), "l"(wv));
            asm("fma.rn.f32x2 %0, %1, %2, %0;" : "+l"(acc[3]) : "l"(pB.y), "l"(wv));
        }
    }
    #pragma unroll
    for (int q = 0; q < 4; q++) {
        float2 v = *(float2*)&acc[q];
        int row = r0 + pg * 8 + q * 2;
        g_part[(size_t)ks * NROWS * SOUT + (size_t)row * SOUT + j]       = v.x;
        g_part[(size_t)ks * NROWS * SOUT + (size_t)(row + 1) * SOUT + j] = v.y;
    }
}

// ---------------- KB: fused reduce + in_proj + conv + x_proj + dt + chunk --
// grid = 192 (one per 8-row sub-chunk), block 256.
__global__ void __launch_bounds__(256) kb_fused(const float* __restrict__ spb,
                                                const float* __restrict__ inw,
                                                const float* __restrict__ convw,
                                                const float* __restrict__ convb,
                                                const float* __restrict__ xpw,
                                                const float* __restrict__ dtw,
                                                const float* __restrict__ dtb,
                                                const float* __restrict__ A_log) {
    __shared__ float sps[11][33];     // s' rows base-3..base+7
    __shared__ float winw[128][33];
    __shared__ float sxpre[11][64];
    __shared__ float sx[8][64];
    __shared__ float xd[8][34];
    __shared__ float sdt[8][64];
    __shared__ float scwT[4][64];
    __shared__ float scb[64], sdtw[128], sdtb[64];

    int tid = threadIdx.x;
    int base = blockIdx.x * 8;
    int b = base / LSEQ;
    int l0 = base % LSEQ;

    // phase 1: reduce KA partials + bias -> s' (zero for invalid halo rows)
    for (int idx = tid; idx < 11 * SOUT; idx += 256) {
        int row = idx >> 5, jj = idx & 31;
        int grow = base + row - 3;
        float v = 0.f;
        if (l0 != 0 || row >= 3) {
            v = spb[jj];
            #pragma unroll
            for (int ks = 0; ks < KSP; ks++)
                v += g_part[(size_t)ks * NROWS * SOUT + (size_t)grow * SOUT + jj];
        }
        sps[row][jj] = v;
    }
    for (int idx = tid; idx < 128 * 32; idx += 256)
        winw[idx >> 5][idx & 31] = inw[idx];
    scwT[tid & 3][tid >> 2] = convw[tid];
    if (tid < 64)        scb[tid] = convb[tid];
    else if (tid < 192)  sdtw[tid - 64] = dtw[tid - 64];
    else                 sdtb[tid - 192] = dtb[tid - 192];
    __syncthreads();

    // phase 2: in_proj GEMM (x part for 11 rows, gate for 8)
    for (int idx = tid; idx < 11 * 64 + 8 * 64; idx += 256) {
        if (idx < 11 * 64) {
            int row = idx >> 6, d = idx & 63;
            float a = 0.f;
            #pragma unroll
            for (int k = 0; k < 32; k++) a = fmaf(sps[row][k], winw[d][k], a);
            sxpre[row][d] = a;
        } else {
            int i2 = idx - 11 * 64;
            int row = i2 >> 6, d = i2 & 63;
            float a = 0.f;
            #pragma unroll
            for (int k = 0; k < 32; k++) a = fmaf(sps[row + 3][k], winw[64 + d][k], a);
            g_gate[(base + row) * DI + d] = a;
        }
    }
    __syncthreads();

    // phase 3: conv + silu (512 elems)
    #pragma unroll
    for (int e = 0; e < 2; e++) {
        int idx = tid + e * 256;
        int r = idx >> 6, d = idx & 63;
        float acc = scb[d];
        #pragma unroll
        for (int kk = 0; kk < 4; kk++) acc = fmaf(sxpre[r + kk][d], scwT[kk][d], acc);
        float xv = acc / (1.f + __expf(-acc));
        sx[r][d] = xv;
        g_x[(base + r) * DI + d] = xv;
    }
    __syncthreads();

    // phase 4: x_proj (8 rows x 34 outs = 272)
    if (tid < 272) {
        int r = tid / 34, jj = tid % 34;
        float a = 0.f;
        #pragma unroll
        for (int dd = 0; dd < 64; dd++) a = fmaf(sx[r][dd], xpw[jj * 64 + dd], a);
        xd[r][jj] = a;
        if (jj >= 18)      g_Cm[(base + r) * DS + (jj - 18)] = a;
        else if (jj >= 2)  g_Bm[(base + r) * DS + (jj - 2)]  = a;
    }
    __syncthreads();

    // phase 5: dt = softplus(...)
    #pragma unroll
    for (int e = 0; e < 2; e++) {
        int idx = tid + e * 256;
        int r = idx >> 6, d = idx & 63;
        float dtraw = fmaf(xd[r][0], sdtw[d * 2],
                      fmaf(xd[r][1], sdtw[d * 2 + 1], sdtb[d]));
        float dtv = fmaxf(dtraw, 0.f) + log1pf(__expf(-fabsf(dtraw)));
        sdt[r][d] = dtv;
        g_dt[(base + r) * DI + d] = dtv;
    }
    __syncthreads();

    // phase 6: this block IS one sub-chunk -> summaries, 4 chains/thread
    {
        int d = tid >> 2;
        int n0 = (tid & 3) * 4;
        float4 al = *(const float4*)(A_log + d * DS + n0);
        float a0 = -__expf(al.x), a1 = -__expf(al.y);
        float a2 = -__expf(al.z), a3 = -__expf(al.w);
        float ra0 = 1.f, ra1 = 1.f, ra2 = 1.f, ra3 = 1.f;
        float rb0 = 0.f, rb1 = 0.f, rb2 = 0.f, rb3 = 0.f;
        #pragma unroll
        for (int t = 0; t < CT; t++) {
            float dtv = sdt[t][d];
            float dtx = dtv * sx[t][d];
            float dA0 = __expf(dtv * a0), dA1 = __expf(dtv * a1);
            float dA2 = __expf(dtv * a2), dA3 = __expf(dtv * a3);
            ra0 *= dA0; ra1 *= dA1; ra2 *= dA2; ra3 *= dA3;
            rb0 = fmaf(dA0, rb0, dtx * xd[t][2 + n0]);
            rb1 = fmaf(dA1, rb1, dtx * xd[t][3 + n0]);
            rb2 = fmaf(dA2, rb2, dtx * xd[t][4 + n0]);
            rb3 = fmaf(dA3, rb3, dtx * xd[t][5 + n0]);
        }
        int c = l0 >> 3;
        size_t o = (size_t)c * CHAINS + b * 1024 + 4 * tid;
        *(float4*)(g_ca + o) = make_float4(ra0, ra1, ra2, ra3);
        *(float4*)(g_cb + o) = make_float4(rb0, rb1, rb2, rb3);
    }
}

// ---------------- K6: fused prefix-combine + scan + gate + out_proj --------
__global__ void __launch_bounds__(512) k6_scan(const float* __restrict__ A_log,
                                               const float* __restrict__ Dp,
                                               const float* __restrict__ opw,
                                               float* __restrict__ out) {
    int b = blockIdx.x / NCH, c = blockIdx.x % NCH;
    int tid = threadIdx.x;
    int d  = tid >> 3;
    int n0 = (tid & 7) * 2;
    __shared__ float sx[CT][DI], sg[CT][DI], sdt[CT][DI];
    __shared__ float sB[CT][DS], sC[CT][DS];
    __shared__ float ysm[CT][DI];
    __shared__ float sop[SOUT][DI + 1];
    int base = b * LSEQ + c * CT;

    {
        int t = tid >> 6, dd = tid & 63;
        sx[t][dd]  = g_x[(base + t) * DI + dd];
        sg[t][dd]  = g_gate[(base + t) * DI + dd];
        sdt[t][dd] = g_dt[(base + t) * DI + dd];
    }
    if (tid < CT * DS) {
        int t = tid >> 4, nn = tid & 15;
        sB[t][nn] = g_Bm[(base + t) * DS + nn];
    } else if (tid < 2 * CT * DS) {
        int i = tid - CT * DS;
        int t = i >> 4, nn = i & 15;
        sC[t][nn] = g_Cm[(base + t) * DS + nn];
    }
    #pragma unroll
    for (int e = 0; e < 4; e++) {
        int idx = tid + e * 512;
        sop[idx >> 6][idx & 63] = opw[idx];
    }

    float h0 = 0.f, h1 = 0.f;
    {
        size_t gc = (size_t)b * 1024 + 2 * tid;
        #pragma unroll 4
        for (int cc = 0; cc < c; cc++) {
            float2 av = *(const float2*)(g_ca + (size_t)cc * CHAINS + gc);
            float2 bv = *(const float2*)(g_cb + (size_t)cc * CHAINS + gc);
            h0 = fmaf(av.x, h0, bv.x);
            h1 = fmaf(av.y, h1, bv.y);
        }
    }
    float2 alv = *(const float2*)(A_log + 2 * tid);
    float a0 = -__expf(alv.x), a1 = -__expf(alv.y);
    float Dv = Dp[d];
    __syncthreads();

    #pragma unroll
    for (int t = 0; t < CT; t++) {
        float dtv = sdt[t][d];
        float xv  = sx[t][d];
        float dtx = dtv * xv;
        float dA0 = __expf(dtv * a0), dA1 = __expf(dtv * a1);
        h0 = fmaf(dA0, h0, dtx * sB[t][n0 + 0]);
        h1 = fmaf(dA1, h1, dtx * sB[t][n0 + 1]);
        float yp = h0 * sC[t][n0 + 0] + h1 * sC[t][n0 + 1];
        yp += __shfl_xor_sync(0xffffffffu, yp, 1);
        yp += __shfl_xor_sync(0xffffffffu, yp, 2);
        yp += __shfl_xor_sync(0xffffffffu, yp, 4);
        if ((tid & 7) == 0) {
            float y = yp + xv * Dv;
            float g = sg[t][d];
            y *= g / (1.f + __expf(-g));
            ysm[t][d] = y;
        }
    }
    __syncthreads();
    if (tid < CT * SOUT) {
        int t = tid >> 5, f = tid & 31;
        float acc = 0.f;
        #pragma unroll
        for (int dd = 0; dd < DI; dd++) acc = fmaf(ysm[t][dd], sop[f][dd], acc);
        out[(size_t)(base + t) * SOUT + f] = acc;
    }
}

// ---------------- K7: z_prime = z*zw + zb + outer(sp, sp) ------------------
// grid = B_ x 192 s-groups(4 rows) x 12 t-strips(64 t) = 4608 blocks; block 256.
// Per thread: 4 si x 2 t = 8 full-line streaming stores. Low regs -> high occ.
__global__ void __launch_bounds__(256) k7_z(const float* __restrict__ z,
                                            const float* __restrict__ zw,
                                            const float* __restrict__ zbv,
                                            const float* __restrict__ sp,
                                            float* __restrict__ outz) {
    int blk = blockIdx.x;
    int b = blk / 2304;
    int rem = blk % 2304;
    int s0 = (rem / 12) * 4;
    int t0 = (rem % 12) * 64;
    int tx = threadIdx.x & 7;       // f-quad
    int tl = threadIdx.x >> 3;      // 0..31
    int tb = t0 + tl * 2;
    const float* zrow = z + (size_t)(b * LSEQ) * LSEQ;
    float* orow = outz + (size_t)(b * LSEQ) * LSEQ * ZF;

    // batch loads
    float2 zq[4];
    #pragma unroll
    for (int si = 0; si < 4; si++)
        zq[si] = *(const float2*)(zrow + (size_t)(s0 + si) * LSEQ + tb);
    float4 sps[4];
    #pragma unroll
    for (int si = 0; si < 4; si++)
        sps[si] = ((const float4*)(sp + (size_t)(b * LSEQ + s0 + si) * SOUT))[tx];
    float4 spt0 = ((const float4*)(sp + (size_t)(b * LSEQ + tb) * SOUT))[tx];
    float4 spt1 = ((const float4*)(sp + (size_t)(b * LSEQ + tb + 1) * SOUT))[tx];
    float4 zw4 = ((const float4*)zw)[tx];
    float4 zb4 = ((const float4*)zbv)[tx];

    #pragma unroll
    for (int si = 0; si < 4; si++) {
        float zv0 = zq[si].x, zv1 = zq[si].y;
        float4 o0, o1;
        o0.x = fmaf(zv0, zw4.x, zb4.x) + sps[si].x * spt0.x;
        o0.y = fmaf(zv0, zw4.y, zb4.y) + sps[si].y * spt0.y;
        o0.z = fmaf(zv0, zw4.z, zb4.z) + sps[si].z * spt0.z;
        o0.w = fmaf(zv0, zw4.w, zb4.w) + sps[si].w * spt0.w;
        o1.x = fmaf(zv1, zw4.x, zb4.x) + sps[si].x * spt1.x;
        o1.y = fmaf(zv1, zw4.y, zb4.y) + sps[si].y * spt1.y;
        o1.z = fmaf(zv1, zw4.z, zb4.z) + sps[si].z * spt1.z;
        o1.w = fmaf(zv1, zw4.w, zb4.w) + sps[si].w * spt1.w;
        size_t rb_ = (size_t)(s0 + si) * LSEQ + tb;
        __stcs((float4*)(orow + rb_ * ZF + tx * 4), o0);
        __stcs((float4*)(orow + (rb_ + 1) * ZF + tx * 4), o1);
    }
}

// ---------------- launch ----------------------------------------------------
extern "C" void kernel_launch(void* const* d_in, const int* in_sizes, int n_in,
                              void* d_out, int out_size) {
    const float* s        = (const float*)d_in[0];
    const float* z        = (const float*)d_in[1];
    const float* s_proj_w = (const float*)d_in[2];
    const float* s_proj_b = (const float*)d_in[3];
    const float* z_proj_w = (const float*)d_in[4];
    const float* z_proj_b = (const float*)d_in[5];
    const float* in_proj_w= (const float*)d_in[6];
    const float* conv_w   = (const float*)d_in[7];
    const float* conv_b   = (const float*)d_in[8];
    const float* x_proj_w = (const float*)d_in[9];
    const float* dt_proj_w= (const float*)d_in[10];
    const float* dt_proj_b= (const float*)d_in[11];
    const float* A_log    = (const float*)d_in[12];
    const float* Dp       = (const float*)d_in[13];
    const float* out_proj_w = (const float*)d_in[14];

    float* out    = (float*)d_out;
    float* sp_out = out;                       // [2,768,32]
    float* z_out  = out + (size_t)B_ * LSEQ * SOUT;

    ka_gemm<<<24 * KSP, 256>>>(s, s_proj_w);
    kb_fused<<<NROWS / 8, 256>>>(s_proj_b, in_proj_w, conv_w, conv_b,
                                 x_proj_w, dt_proj_w, dt_proj_b, A_log);
    k6_scan<<<B_ * NCH, 512>>>(A_log, Dp, out_proj_w, sp_out);
    k7_z<<<4608, 256>>>(z, z_proj_w, z_proj_b, sp_out, z_out);
}

// round 10
// speedup vs baseline: 2.8865x; 1.0199x over previous
#include <cuda_runtime.h>

#define B_   2
#define LSEQ 768
#define SIN  1280
#define SOUT 32
#define ZF   32
#define DI   64
#define DS   16
#define NCH  96     // sub-chunks along L
#define CT   8      // sub-chunk length
#define NROWS (B_*LSEQ)          // 1536
#define CHAINS (B_*DI*DS)        // 2048
#define KSP  8      // split-K for phase A
#define KCA  (SIN/KSP)           // 160
#define NBLK 96

// ---------------- scratch -----------------------------------------------
__device__ float g_part[KSP*NROWS*SOUT];   // phase-A partials (1.5 MB)
__device__ float g_x[NROWS*DI];
__device__ float g_gate[NROWS*DI];
__device__ float g_dt[NROWS*DI];
__device__ float g_Bm[NROWS*DS];
__device__ float g_Cm[NROWS*DS];
__device__ float g_ca[NCH*CHAINS];
__device__ float g_cb[NCH*CHAINS];

// ---------------- software grid barrier (96 blocks, all resident) ---------
__device__ unsigned g_bar_count = 0;
__device__ volatile unsigned g_bar_gen = 0;

__device__ __forceinline__ void grid_barrier() {
    __syncthreads();
    if (threadIdx.x == 0) {
        __threadfence();
        unsigned gen = g_bar_gen;
        if (atomicAdd(&g_bar_count, 1u) == NBLK - 1u) {
            g_bar_count = 0;
            __threadfence();
            g_bar_gen = gen + 1;
        } else {
            while (g_bar_gen == gen) { }
            __threadfence();
        }
    }
    __syncthreads();
}

// ---------------- shared-memory phase union --------------------------------
struct PhaseA { float sT[32][68]; float wdup[32][64]; };
struct PhaseB { float sps[11][33]; float sxpre[11][64]; float sx[8][64];
                float xd[8][34]; float sdt[8][64]; };
struct PhaseC { float sx[8][64]; float sg[8][64]; float sdt[8][64];
                float sB[8][16]; float sC[8][16]; float ysm[8][64]; };
union SmemU {
    PhaseA a[2];
    struct { PhaseB b[2]; float winw[128][33]; float scwT[4][64];
             float scb[64]; float sdtw[128]; float sdtb[64]; } pb;
    struct { PhaseC c[2]; float sop[32][65]; } pc;
};

// ---------------- mamba_one: entire s' pipeline in one kernel --------------
// grid = 96 blocks x 512 threads; each block = 2 units of 256 threads.
__global__ void __launch_bounds__(512) mamba_one(
    const float* __restrict__ s,    const float* __restrict__ spw,
    const float* __restrict__ spb,  const float* __restrict__ inw,
    const float* __restrict__ convw,const float* __restrict__ convb,
    const float* __restrict__ xpw,  const float* __restrict__ dtw,
    const float* __restrict__ dtb,  const float* __restrict__ A_log,
    const float* __restrict__ Dp,   const float* __restrict__ opw,
    float* __restrict__ out)
{
    __shared__ SmemU un;
    int tid  = threadIdx.x;
    int u    = tid >> 8;
    int utid = tid & 255;

    // =================== phase A: s' partials (split-K GEMM) ===============
    {
        PhaseA& A = un.a[u];
        int unit = blockIdx.x * 2 + u;          // 0..191
        int rt = unit >> 3, ks = unit & 7;
        int r0 = rt * 64, kb = ks * KCA;
        int j  = utid & 31;
        int pg = utid >> 5;
        unsigned long long acc[4] = {0ull, 0ull, 0ull, 0ull};
        int lrow = utid >> 3, lk4 = (utid & 7) * 4;
        int wj   = utid >> 3, wk4 = (utid & 7) * 4;

        #pragma unroll 1
        for (int tile = 0; tile < KCA / 32; tile++) {
            int ktb = kb + tile * 32;
            __syncthreads();
            #pragma unroll
            for (int half = 0; half < 2; half++) {
                int row = lrow + half * 32;
                float4 v = *(const float4*)(s + (size_t)(r0 + row) * SIN + ktb + lk4);
                A.sT[lk4 + 0][row] = v.x; A.sT[lk4 + 1][row] = v.y;
                A.sT[lk4 + 2][row] = v.z; A.sT[lk4 + 3][row] = v.w;
            }
            {
                float4 w = *(const float4*)(spw + (size_t)wj * SIN + ktb + wk4);
                A.wdup[wk4 + 0][2 * wj] = w.x; A.wdup[wk4 + 0][2 * wj + 1] = w.x;
                A.wdup[wk4 + 1][2 * wj] = w.y; A.wdup[wk4 + 1][2 * wj + 1] = w.y;
                A.wdup[wk4 + 2][2 * wj] = w.z; A.wdup[wk4 + 2][2 * wj + 1] = w.z;
                A.wdup[wk4 + 3][2 * wj] = w.w; A.wdup[wk4 + 3][2 * wj + 1] = w.w;
            }
            __syncthreads();
            #pragma unroll
            for (int k = 0; k < 32; k++) {
                ulonglong2 pA = *(const ulonglong2*)&A.sT[k][pg * 8];
                ulonglong2 pB = *(const ulonglong2*)&A.sT[k][pg * 8 + 4];
                unsigned long long wv = *(const unsigned long long*)&A.wdup[k][2 * j];
                asm("fma.rn.f32x2 %0, %1, %2, %0;" : "+l"(acc[0]) : "l"(pA.x), "l"(wv));
                asm("fma.rn.f32x2 %0, %1, %2, %0;" : "+l"(acc[1]) : "l"(pA.y), "l"(wv));
                asm("fma.rn.f32x2 %0, %1, %2, %0;" : "+l"(acc[2]) : "l"(pB.x), "l"(wv));
                asm("fma.rn.f32x2 %0, %1, %2, %0;" : "+l"(acc[3]) : "l"(pB.y), "l"(wv));
            }
        }
        #pragma unroll
        for (int q = 0; q < 4; q++) {
            float2 v = *(float2*)&acc[q];
            int row = r0 + pg * 8 + q * 2;
            g_part[(size_t)ks * NROWS * SOUT + (size_t)row * SOUT + j]       = v.x;
            g_part[(size_t)ks * NROWS * SOUT + (size_t)(row + 1) * SOUT + j] = v.y;
        }
    }
    grid_barrier();

    // =================== phase B: reduce + in_proj + conv + x_proj + dt ====
    {
        PhaseB& Bv = un.pb.b[u];
        int cu = blockIdx.x * 2 + u;            // sub-chunk 0..191
        int base = cu * 8;
        int l0 = base % LSEQ;

        // shared weights (whole block)
        for (int idx = tid; idx < 128 * 32; idx += 512)
            un.pb.winw[idx >> 5][idx & 31] = inw[idx];
        if (tid < 256)        un.pb.scwT[tid & 3][tid >> 2] = convw[tid];
        else if (tid < 320)   un.pb.scb[tid - 256] = convb[tid - 256];
        else if (tid < 448)   un.pb.sdtw[tid - 320] = dtw[tid - 320];
        else                  un.pb.sdtb[tid - 448] = dtb[tid - 448];

        // reduce partials + bias -> s' (zero halo)
        for (int idx = utid; idx < 11 * SOUT; idx += 256) {
            int row = idx >> 5, jj = idx & 31;
            int grow = base + row - 3;
            float v = 0.f;
            if (l0 != 0 || row >= 3) {
                v = spb[jj];
                #pragma unroll
                for (int ks = 0; ks < KSP; ks++)
                    v += g_part[(size_t)ks * NROWS * SOUT + (size_t)grow * SOUT + jj];
            }
            Bv.sps[row][jj] = v;
        }
        __syncthreads();

        // in_proj GEMM (x for 11 rows, gate for 8)
        for (int idx = utid; idx < 11 * 64 + 8 * 64; idx += 256) {
            if (idx < 11 * 64) {
                int row = idx >> 6, d = idx & 63;
                float a = 0.f;
                #pragma unroll
                for (int k = 0; k < 32; k++) a = fmaf(Bv.sps[row][k], un.pb.winw[d][k], a);
                Bv.sxpre[row][d] = a;
            } else {
                int i2 = idx - 11 * 64;
                int row = i2 >> 6, d = i2 & 63;
                float a = 0.f;
                #pragma unroll
                for (int k = 0; k < 32; k++) a = fmaf(Bv.sps[row + 3][k], un.pb.winw[64 + d][k], a);
                g_gate[(base + row) * DI + d] = a;
            }
        }
        __syncthreads();

        // conv + silu
        #pragma unroll
        for (int e = 0; e < 2; e++) {
            int idx = utid + e * 256;
            int r = idx >> 6, d = idx & 63;
            float acc = un.pb.scb[d];
            #pragma unroll
            for (int kk = 0; kk < 4; kk++)
                acc = fmaf(Bv.sxpre[r + kk][d], un.pb.scwT[kk][d], acc);
            float xv = acc / (1.f + __expf(-acc));
            Bv.sx[r][d] = xv;
            g_x[(base + r) * DI + d] = xv;
        }
        __syncthreads();

        // x_proj (8 rows x 34 outs = 272; LOOP, not if — fixes missing outputs)
        for (int idx = utid; idx < 272; idx += 256) {
            int r = idx / 34, jj = idx % 34;
            float a = 0.f;
            #pragma unroll
            for (int dd = 0; dd < 64; dd++) a = fmaf(Bv.sx[r][dd], xpw[jj * 64 + dd], a);
            Bv.xd[r][jj] = a;
            if (jj >= 18)      g_Cm[(base + r) * DS + (jj - 18)] = a;
            else if (jj >= 2)  g_Bm[(base + r) * DS + (jj - 2)]  = a;
        }
        __syncthreads();

        // dt = softplus(...)
        #pragma unroll
        for (int e = 0; e < 2; e++) {
            int idx = utid + e * 256;
            int r = idx >> 6, d = idx & 63;
            float dtraw = fmaf(Bv.xd[r][0], un.pb.sdtw[d * 2],
                          fmaf(Bv.xd[r][1], un.pb.sdtw[d * 2 + 1], un.pb.sdtb[d]));
            float dtv = fmaxf(dtraw, 0.f) + log1pf(__expf(-fabsf(dtraw)));
            Bv.sdt[r][d] = dtv;
            g_dt[(base + r) * DI + d] = dtv;
        }
        __syncthreads();

        // sub-chunk summaries, 4 chains/thread
        {
            int d = utid >> 2;
            int n0 = (utid & 3) * 4;
            float4 al = *(const float4*)(A_log + d * DS + n0);
            float a0 = -__expf(al.x), a1 = -__expf(al.y);
            float a2 = -__expf(al.z), a3 = -__expf(al.w);
            float ra0 = 1.f, ra1 = 1.f, ra2 = 1.f, ra3 = 1.f;
            float rb0 = 0.f, rb1 = 0.f, rb2 = 0.f, rb3 = 0.f;
            #pragma unroll
            for (int t = 0; t < CT; t++) {
                float dtv = Bv.sdt[t][d];
                float dtx = dtv * Bv.sx[t][d];
                float dA0 = __expf(dtv * a0), dA1 = __expf(dtv * a1);
                float dA2 = __expf(dtv * a2), dA3 = __expf(dtv * a3);
                ra0 *= dA0; ra1 *= dA1; ra2 *= dA2; ra3 *= dA3;
                rb0 = fmaf(dA0, rb0, dtx * Bv.xd[t][2 + n0]);
                rb1 = fmaf(dA1, rb1, dtx * Bv.xd[t][3 + n0]);
                rb2 = fmaf(dA2, rb2, dtx * Bv.xd[t][4 + n0]);
                rb3 = fmaf(dA3, rb3, dtx * Bv.xd[t][5 + n0]);
            }
            int b = base / LSEQ, c = (base % LSEQ) >> 3;
            size_t o = (size_t)c * CHAINS + b * 1024 + 4 * utid;
            *(float4*)(g_ca + o) = make_float4(ra0, ra1, ra2, ra3);
            *(float4*)(g_cb + o) = make_float4(rb0, rb1, rb2, rb3);
        }
    }
    grid_barrier();

    // =================== phase C: prefix-combine + scan + gate + out_proj ==
    {
        PhaseC& C = un.pc.c[u];
        int cu = blockIdx.x * 2 + u;
        int b = cu / NCH, c = cu % NCH;
        int base = cu * 8;

        for (int e = 0; e < 4; e++) {            // sop: 2048 elems, 512 thr
            int idx = tid + e * 512;
            un.pc.sop[idx >> 6][idx & 63] = opw[idx];
        }
        #pragma unroll
        for (int e = 0; e < 2; e++) {            // stage tiles
            int idx = utid + e * 256;
            int t = idx >> 6, dd = idx & 63;
            C.sx[t][dd]  = g_x[(base + t) * DI + dd];
            C.sg[t][dd]  = g_gate[(base + t) * DI + dd];
            C.sdt[t][dd] = g_dt[(base + t) * DI + dd];
        }
        if (utid < 128) {
            int t = utid >> 4, nn = utid & 15;
            C.sB[t][nn] = g_Bm[(base + t) * DS + nn];
            C.sC[t][nn] = g_Cm[(base + t) * DS + nn];
        }

        int d = utid >> 2;
        int n0 = (utid & 3) * 4;
        float4 al = *(const float4*)(A_log + 4 * utid);
        float a0 = -__expf(al.x), a1 = -__expf(al.y);
        float a2 = -__expf(al.z), a3 = -__expf(al.w);
        float h0 = 0.f, h1 = 0.f, h2 = 0.f, h3 = 0.f;
        {
            size_t gc = (size_t)b * 1024 + 4 * utid;
            #pragma unroll 4
            for (int cc = 0; cc < c; cc++) {
                float4 av = *(const float4*)(g_ca + (size_t)cc * CHAINS + gc);
                float4 bv = *(const float4*)(g_cb + (size_t)cc * CHAINS + gc);
                h0 = fmaf(av.x, h0, bv.x);
                h1 = fmaf(av.y, h1, bv.y);
                h2 = fmaf(av.z, h2, bv.z);
                h3 = fmaf(av.w, h3, bv.w);
            }
        }
        float Dv = Dp[d];
        __syncthreads();

        #pragma unroll
        for (int t = 0; t < CT; t++) {
            float dtv = C.sdt[t][d];
            float xv  = C.sx[t][d];
            float dtx = dtv * xv;
            float dA0 = __expf(dtv * a0), dA1 = __expf(dtv * a1);
            float dA2 = __expf(dtv * a2), dA3 = __expf(dtv * a3);
            h0 = fmaf(dA0, h0, dtx * C.sB[t][n0 + 0]);
            h1 = fmaf(dA1, h1, dtx * C.sB[t][n0 + 1]);
            h2 = fmaf(dA2, h2, dtx * C.sB[t][n0 + 2]);
            h3 = fmaf(dA3, h3, dtx * C.sB[t][n0 + 3]);
            float yp = h0 * C.sC[t][n0 + 0] + h1 * C.sC[t][n0 + 1]
                     + h2 * C.sC[t][n0 + 2] + h3 * C.sC[t][n0 + 3];
            yp += __shfl_xor_sync(0xffffffffu, yp, 1);
            yp += __shfl_xor_sync(0xffffffffu, yp, 2);
            if ((utid & 3) == 0) {
                float y = yp + xv * Dv;
                float g = C.sg[t][d];
                y *= g / (1.f + __expf(-g));
                C.ysm[t][d] = y;
            }
        }
        __syncthreads();
        {   // out_proj: 256 threads = 8 t x 32 f
            int t = utid >> 5, f = utid & 31;
            float acc = 0.f;
            #pragma unroll
            for (int dd = 0; dd < DI; dd++)
                acc = fmaf(C.ysm[t][dd], un.pc.sop[f][dd], acc);
            out[(size_t)(base + t) * SOUT + f] = acc;
        }
    }
}

// ---------------- K7: z_prime = z*zw + zb + outer(sp, sp) ------------------
// grid = B_ x 192 s-groups(4 rows) x 12 t-strips(64 t) = 4608 blocks; block 256.
__global__ void __launch_bounds__(256) k7_z(const float* __restrict__ z,
                                            const float* __restrict__ zw,
                                            const float* __restrict__ zbv,
                                            const float* __restrict__ sp,
                                            float* __restrict__ outz) {
    int blk = blockIdx.x;
    int b = blk / 2304;
    int rem = blk % 2304;
    int s0 = (rem / 12) * 4;
    int t0 = (rem % 12) * 64;
    int tx = threadIdx.x & 7;
    int tl = threadIdx.x >> 3;
    int tb = t0 + tl * 2;
    const float* zrow = z + (size_t)(b * LSEQ) * LSEQ;
    float* orow = outz + (size_t)(b * LSEQ) * LSEQ * ZF;

    float2 zq[4];
    #pragma unroll
    for (int si = 0; si < 4; si++)
        zq[si] = *(const float2*)(zrow + (size_t)(s0 + si) * LSEQ + tb);
    float4 sps[4];
    #pragma unroll
    for (int si = 0; si < 4; si++)
        sps[si] = ((const float4*)(sp + (size_t)(b * LSEQ + s0 + si) * SOUT))[tx];
    float4 spt0 = ((const float4*)(sp + (size_t)(b * LSEQ + tb) * SOUT))[tx];
    float4 spt1 = ((const float4*)(sp + (size_t)(b * LSEQ + tb + 1) * SOUT))[tx];
    float4 zw4 = ((const float4*)zw)[tx];
    float4 zb4 = ((const float4*)zbv)[tx];

    #pragma unroll
    for (int si = 0; si < 4; si++) {
        float zv0 = zq[si].x, zv1 = zq[si].y;
        float4 o0, o1;
        o0.x = fmaf(zv0, zw4.x, zb4.x) + sps[si].x * spt0.x;
        o0.y = fmaf(zv0, zw4.y, zb4.y) + sps[si].y * spt0.y;
        o0.z = fmaf(zv0, zw4.z, zb4.z) + sps[si].z * spt0.z;
        o0.w = fmaf(zv0, zw4.w, zb4.w) + sps[si].w * spt0.w;
        o1.x = fmaf(zv1, zw4.x, zb4.x) + sps[si].x * spt1.x;
        o1.y = fmaf(zv1, zw4.y, zb4.y) + sps[si].y * spt1.y;
        o1.z = fmaf(zv1, zw4.z, zb4.z) + sps[si].z * spt1.z;
        o1.w = fmaf(zv1, zw4.w, zb4.w) + sps[si].w * spt1.w;
        size_t rb_ = (size_t)(s0 + si) * LSEQ + tb;
        __stcs((float4*)(orow + rb_ * ZF + tx * 4), o0);
        __stcs((float4*)(orow + (rb_ + 1) * ZF + tx * 4), o1);
    }
}

// ---------------- launch ----------------------------------------------------
extern "C" void kernel_launch(void* const* d_in, const int* in_sizes, int n_in,
                              void* d_out, int out_size) {
    const float* s        = (const float*)d_in[0];
    const float* z        = (const float*)d_in[1];
    const float* s_proj_w = (const float*)d_in[2];
    const float* s_proj_b = (const float*)d_in[3];
    const float* z_proj_w = (const float*)d_in[4];
    const float* z_proj_b = (const float*)d_in[5];
    const float* in_proj_w= (const float*)d_in[6];
    const float* conv_w   = (const float*)d_in[7];
    const float* conv_b   = (const float*)d_in[8];
    const float* x_proj_w = (const float*)d_in[9];
    const float* dt_proj_w= (const float*)d_in[10];
    const float* dt_proj_b= (const float*)d_in[11];
    const float* A_log    = (const float*)d_in[12];
    const float* Dp       = (const float*)d_in[13];
    const float* out_proj_w = (const float*)d_in[14];

    float* out    = (float*)d_out;
    float* sp_out = out;                       // [2,768,32]
    float* z_out  = out + (size_t)B_ * LSEQ * SOUT;

    mamba_one<<<NBLK, 512>>>(s, s_proj_w, s_proj_b, in_proj_w, conv_w, conv_b,
                             x_proj_w, dt_proj_w, dt_proj_b, A_log, Dp,
                             out_proj_w, sp_out);
    k7_z<<<4608, 256>>>(z, z_proj_w, z_proj_b, sp_out, z_out);
}